// round 1
// baseline (speedup 1.0000x reference)
#include <cuda_runtime.h>

#define NX    16384
#define BB    8
#define CI    32
#define CO    32
#define H1D   64
#define H2D   128
#define NBO   (BB*CO)      // 256
#define NBI   (BB*CI)      // 256
#define KSPLIT 64          // split-K for T gemm

// ---------------- device scratch (no allocations allowed) ----------------
__device__ float g_H2phiT[H2D * NX];              // [k][n]  8.4 MB
__device__ float g_H2psiT[H2D * NX];              // [k][m]  8.4 MB
__device__ float g_Tpart[KSPLIT * NBI * H2D];     // split-K partials 8.4 MB
__device__ float g_xsumpart[KSPLIT * NBI];
__device__ float g_T[NBI * H2D];                  // [b*CI+i][k]
__device__ float g_xsum[NBI];
__device__ float g_U[NBO * H2D];                  // [b*CO+o][k] (pre-scaled 1/Nx)
__device__ float g_c[NBO];                        // (pre-scaled 1/Nx)

// ---------------- K1: coordinate MLP hidden layers -> H2^T ----------------
// One thread per grid point n; block = 128 threads; gridDim.y selects phi/psi.
__global__ __launch_bounds__(128) void k_mlp(
    const float* __restrict__ w1p, const float* __restrict__ b1p,
    const float* __restrict__ w2p, const float* __restrict__ b2p,
    const float* __restrict__ w1q, const float* __restrict__ b1q,
    const float* __restrict__ w2q, const float* __restrict__ b2q)
{
    __shared__ float sW2T[H2D * 68];   // [k][j], pad 68 (rows 272B, 16B aligned)
    __shared__ float sW1[2 * H1D];
    __shared__ float sB1[H1D];
    __shared__ float sB2[H2D];

    const float* w1 = blockIdx.y ? w1q : w1p;
    const float* b1 = blockIdx.y ? b1q : b1p;
    const float* w2 = blockIdx.y ? w2q : w2p;
    const float* b2 = blockIdx.y ? b2q : b2p;
    float* out = blockIdx.y ? g_H2psiT : g_H2phiT;

    int t = threadIdx.x;
    for (int idx = t; idx < H1D * H2D; idx += 128) {
        int j = idx >> 7, k = idx & 127;          // w2 is [j][k], coalesced over k
        sW2T[k * 68 + j] = w2[idx];
    }
    if (t < 2 * H1D) sW1[t] = w1[t];
    if (t < H1D)     sB1[t] = b1[t];
    if (t < H2D)     sB2[t] = b2[t];
    __syncthreads();

    int n = blockIdx.x * 128 + t;
    const float inv = 1.0f / 127.0f;
    float gx = (float)(n >> 7) * inv;
    float gy = (float)(n & 127) * inv;

    float h1[H1D];
#pragma unroll
    for (int j = 0; j < H1D; j++) {
        float v = fmaf(gx, sW1[j], fmaf(gy, sW1[H1D + j], sB1[j]));
        h1[j] = fmaxf(v, 0.0f);
    }

    for (int k = 0; k < H2D; k++) {
        float acc = sB2[k];
        const float4* w4 = (const float4*)(&sW2T[k * 68]);
#pragma unroll
        for (int j4 = 0; j4 < 16; j4++) {
            float4 w = w4[j4];
            acc = fmaf(h1[4 * j4 + 0], w.x, acc);
            acc = fmaf(h1[4 * j4 + 1], w.y, acc);
            acc = fmaf(h1[4 * j4 + 2], w.z, acc);
            acc = fmaf(h1[4 * j4 + 3], w.w, acc);
        }
        out[k * NX + n] = fmaxf(acc, 0.0f);       // coalesced over n
    }
}

// ---------------- K2: T-partials  C[256,128] = x[256,16384] @ H2phi[16384,128] ----
// grid (8 row tiles, 64 k-splits), 128 threads, thread tile = 8 rows x 4 k.
__global__ __launch_bounds__(128) void k_gemmT(const float* __restrict__ x)
{
    __shared__ float sx[64 * 36];      // [nn][r] pad 36 (rows 144B, 16B aligned)
    __shared__ float sw[64 * 132];     // [nn][k] pad 132 (rows 528B, 16B aligned)

    int t = threadIdx.x;
    int row0  = blockIdx.x * 32;
    int nbase = blockIdx.y * (NX / KSPLIT);       // 256-wide K range
    int kg = t & 31;                               // k = 4*kg .. 4*kg+3
    int rg = t >> 5;                               // rows rg*8 .. rg*8+7

    float acc[8][4];
#pragma unroll
    for (int a = 0; a < 8; a++)
#pragma unroll
        for (int b = 0; b < 4; b++) acc[a][b] = 0.0f;
    float xs = 0.0f;

    for (int chunk = 0; chunk < 4; chunk++) {
        int nb = nbase + chunk * 64;
        __syncthreads();
        for (int idx = t; idx < 32 * 64; idx += 128) {
            int n = idx & 63, r = idx >> 6;        // coalesced over n
            sx[n * 36 + r] = x[(row0 + r) * NX + nb + n];
        }
        for (int idx = t; idx < 128 * 64; idx += 128) {
            int n = idx & 63, k = idx >> 6;        // coalesced over n
            sw[n * 132 + k] = g_H2phiT[k * NX + nb + n];
        }
        __syncthreads();

        if (t < 32) {                              // x row-sum partial
            float s = 0.0f;
            for (int n = 0; n < 64; n++) s += sx[n * 36 + t];
            xs += s;
        }

#pragma unroll 2
        for (int nn = 0; nn < 64; nn++) {
            float4 w  = *(const float4*)(&sw[nn * 132 + 4 * kg]);
            float4 xa = *(const float4*)(&sx[nn * 36 + rg * 8]);
            float4 xb = *(const float4*)(&sx[nn * 36 + rg * 8 + 4]);
            float xr[8] = {xa.x, xa.y, xa.z, xa.w, xb.x, xb.y, xb.z, xb.w};
            float wr[4] = {w.x, w.y, w.z, w.w};
#pragma unroll
            for (int rr = 0; rr < 8; rr++)
#pragma unroll
                for (int kj = 0; kj < 4; kj++)
                    acc[rr][kj] = fmaf(xr[rr], wr[kj], acc[rr][kj]);
        }
    }

    float* dst = &g_Tpart[blockIdx.y * (NBI * H2D)];
#pragma unroll
    for (int rr = 0; rr < 8; rr++) {
        float4 v = make_float4(acc[rr][0], acc[rr][1], acc[rr][2], acc[rr][3]);
        *(float4*)(&dst[(row0 + rg * 8 + rr) * H2D + 4 * kg]) = v;
    }
    if (t < 32) g_xsumpart[blockIdx.y * NBI + row0 + t] = xs;
}

// ---------------- K2b: reduce split-K partials (deterministic) ----------------
__global__ __launch_bounds__(256) void k_reduce()
{
    int i = blockIdx.x * blockDim.x + threadIdx.x;
    if (i < NBI * H2D) {
        float s = 0.0f;
        for (int sp = 0; sp < KSPLIT; sp++) s += g_Tpart[sp * (NBI * H2D) + i];
        g_T[i] = s;
    }
    if (i < NBI) {
        float s = 0.0f;
        for (int sp = 0; sp < KSPLIT; sp++) s += g_xsumpart[sp * NBI + i];
        g_xsum[i] = s;
    }
}

// ---------------- K3: s, U, c (tiny contractions over i/k) ----------------
// block per (b,o); 128 threads.
__global__ __launch_bounds__(128) void k_small(
    const float* __restrict__ w3p, const float* __restrict__ b3p,
    const float* __restrict__ w3q, const float* __restrict__ b3q)
{
    __shared__ float sS[CI];
    int bo = blockIdx.x;
    int b = bo >> 5, o = bo & 31;
    int t = threadIdx.x;

    if (t < CI) {
        int col = o * CI + t;
        float acc = b3p[col] * g_xsum[b * CI + t];
        const float* Trow = &g_T[(b * CI + t) * H2D];
        for (int k = 0; k < H2D; k++)
            acc = fmaf(Trow[k], w3p[k * (CO * CI) + col], acc);
        sS[t] = acc;
    }
    __syncthreads();

    {   // U[bo][k], one thread per k
        int k = t;
        float u = 0.0f;
#pragma unroll
        for (int i = 0; i < CI; i++)
            u = fmaf(sS[i], w3q[k * (CO * CI) + o * CI + i], u);
        g_U[bo * H2D + k] = u * (1.0f / (float)NX);
    }
    if (t == 0) {
        float c = 0.0f;
        for (int i = 0; i < CI; i++) c = fmaf(sS[i], b3q[o * CI + i], c);
        g_c[bo] = c * (1.0f / (float)NX);
    }
}

// ---------------- K4: out[bo][m] = U[bo][:] @ H2psi^T[:, m] + c[bo] ----------
// grid (64 m-tiles, 8 bo-tiles), 256 threads, thread tile = 8 bo x 4 m.
__global__ __launch_bounds__(256) void k_out(float* __restrict__ out)
{
    __shared__ float sU[32 * H2D];     // 16 KB
    __shared__ float sH[32 * 256];     // 32 KB (one k-chunk x 256 m)

    int t = threadIdx.x;
    int m0  = blockIdx.x * 256;
    int bo0 = blockIdx.y * 32;
    int mg = t & 63;                   // m = m0 + 4*mg
    int bg = t >> 6;                   // bo = bo0 + bg*8 + bb

    for (int idx = t; idx < 32 * H2D; idx += 256)
        sU[idx] = g_U[bo0 * H2D + idx];

    float acc[8][4];
#pragma unroll
    for (int a = 0; a < 8; a++)
#pragma unroll
        for (int b = 0; b < 4; b++) acc[a][b] = 0.0f;

    for (int kc = 0; kc < 4; kc++) {
        __syncthreads();
        for (int idx = t; idx < 32 * 256; idx += 256) {
            int mm = idx & 255, kk = idx >> 8;     // coalesced over m
            sH[kk * 256 + mm] = g_H2psiT[(kc * 32 + kk) * NX + m0 + mm];
        }
        __syncthreads();

#pragma unroll
        for (int k4 = 0; k4 < 8; k4++) {
            float4 uu[8];
#pragma unroll
            for (int bb = 0; bb < 8; bb++)
                uu[bb] = *(const float4*)(&sU[(bg * 8 + bb) * H2D + kc * 32 + 4 * k4]);
            float4 hh[4];
#pragma unroll
            for (int j = 0; j < 4; j++)
                hh[j] = *(const float4*)(&sH[(4 * k4 + j) * 256 + 4 * mg]);
#pragma unroll
            for (int bb = 0; bb < 8; bb++) {
                acc[bb][0] = fmaf(uu[bb].x, hh[0].x, acc[bb][0]);
                acc[bb][1] = fmaf(uu[bb].x, hh[0].y, acc[bb][1]);
                acc[bb][2] = fmaf(uu[bb].x, hh[0].z, acc[bb][2]);
                acc[bb][3] = fmaf(uu[bb].x, hh[0].w, acc[bb][3]);
                acc[bb][0] = fmaf(uu[bb].y, hh[1].x, acc[bb][0]);
                acc[bb][1] = fmaf(uu[bb].y, hh[1].y, acc[bb][1]);
                acc[bb][2] = fmaf(uu[bb].y, hh[1].z, acc[bb][2]);
                acc[bb][3] = fmaf(uu[bb].y, hh[1].w, acc[bb][3]);
                acc[bb][0] = fmaf(uu[bb].z, hh[2].x, acc[bb][0]);
                acc[bb][1] = fmaf(uu[bb].z, hh[2].y, acc[bb][1]);
                acc[bb][2] = fmaf(uu[bb].z, hh[2].z, acc[bb][2]);
                acc[bb][3] = fmaf(uu[bb].z, hh[2].w, acc[bb][3]);
                acc[bb][0] = fmaf(uu[bb].w, hh[3].x, acc[bb][0]);
                acc[bb][1] = fmaf(uu[bb].w, hh[3].y, acc[bb][1]);
                acc[bb][2] = fmaf(uu[bb].w, hh[3].z, acc[bb][2]);
                acc[bb][3] = fmaf(uu[bb].w, hh[3].w, acc[bb][3]);
            }
        }
    }

#pragma unroll
    for (int bb = 0; bb < 8; bb++) {
        int bo = bo0 + bg * 8 + bb;
        float cc = g_c[bo];
        float4 v = make_float4(acc[bb][0] + cc, acc[bb][1] + cc,
                               acc[bb][2] + cc, acc[bb][3] + cc);
        *(float4*)(&out[bo * NX + m0 + 4 * mg]) = v;    // coalesced
    }
}

// ---------------- launch ----------------
extern "C" void kernel_launch(void* const* d_in, const int* in_sizes, int n_in,
                              void* d_out, int out_size)
{
    const float* x      = (const float*)d_in[0];
    const float* phi_w1 = (const float*)d_in[1];
    const float* phi_b1 = (const float*)d_in[2];
    const float* phi_w2 = (const float*)d_in[3];
    const float* phi_b2 = (const float*)d_in[4];
    const float* phi_w3 = (const float*)d_in[5];
    const float* phi_b3 = (const float*)d_in[6];
    const float* psi_w1 = (const float*)d_in[7];
    const float* psi_b1 = (const float*)d_in[8];
    const float* psi_w2 = (const float*)d_in[9];
    const float* psi_b2 = (const float*)d_in[10];
    const float* psi_w3 = (const float*)d_in[11];
    const float* psi_b3 = (const float*)d_in[12];
    float* out = (float*)d_out;

    k_mlp<<<dim3(NX / 128, 2), 128>>>(phi_w1, phi_b1, phi_w2, phi_b2,
                                      psi_w1, psi_b1, psi_w2, psi_b2);
    k_gemmT<<<dim3(NBI / 32, KSPLIT), 128>>>(x);
    k_reduce<<<(NBI * H2D + 255) / 256, 256>>>();
    k_small<<<NBO, 128>>>(phi_w3, phi_b3, psi_w3, psi_b3);
    k_out<<<dim3(NX / 256, NBO / 32), 256>>>(out);
}

// round 5
// speedup vs baseline: 1.4249x; 1.4249x over previous
#include <cuda_runtime.h>
#include <cuda_bf16.h>
#include <cstdint>

#define NX    16384
#define CI    32
#define CO    32
#define H1D   64
#define H2D   128
#define NBI   256
#define NBO   256
#define KSPLIT 64

// ---------------- device scratch ----------------
__device__ __nv_bfloat16 g_Bphi_hi[H2D * NX];   // [k][n] phi hidden (relu'd), bf16 hi
__device__ __nv_bfloat16 g_Bphi_lo[H2D * NX];   // residual
__device__ __nv_bfloat16 g_Apsi_hi[NX * H2D];   // [m][k] psi hidden, bf16 hi
__device__ __nv_bfloat16 g_Apsi_lo[NX * H2D];
__device__ float g_Tpart[KSPLIT * NBI * H2D];   // [sp][bi][k]
__device__ float g_T[NBI * H2D];                // [bi][k]
__device__ float g_xsum[NBI];
__device__ float g_S[8 * CO * CI];              // [b][o*32+i]
__device__ float g_U[NBO * H2D];                // [b*32+o][k] (scaled 1/NX)
__device__ float g_c[NBO];                      // (scaled 1/NX)

// ---------------- helpers ----------------
__device__ __forceinline__ uint32_t smem_u32(const void* p) {
    uint32_t a;
    asm("{ .reg .u64 t; cvta.to.shared.u64 t, %1; cvt.u32.u64 %0, t; }" : "=r"(a) : "l"(p));
    return a;
}
__device__ __forceinline__ void ldm4(uint32_t* r, uint32_t addr) {
    asm volatile("ldmatrix.sync.aligned.m8n8.x4.shared.b16 {%0,%1,%2,%3}, [%4];"
                 : "=r"(r[0]), "=r"(r[1]), "=r"(r[2]), "=r"(r[3]) : "r"(addr));
}
__device__ __forceinline__ void mma_bf16(float* c, const uint32_t* a, uint32_t b0, uint32_t b1) {
    asm volatile("mma.sync.aligned.m16n8k16.row.col.f32.bf16.bf16.f32 "
                 "{%0,%1,%2,%3}, {%4,%5,%6,%7}, {%8,%9}, {%0,%1,%2,%3};"
                 : "+f"(c[0]), "+f"(c[1]), "+f"(c[2]), "+f"(c[3])
                 : "r"(a[0]), "r"(a[1]), "r"(a[2]), "r"(a[3]), "r"(b0), "r"(b1));
}
__device__ __forceinline__ uint32_t pack2(__nv_bfloat16 a, __nv_bfloat16 b) {
    return (uint32_t)__bfloat16_as_ushort(a) | ((uint32_t)__bfloat16_as_ushort(b) << 16);
}
__device__ __forceinline__ void split1(float v, __nv_bfloat16& h, __nv_bfloat16& l) {
    h = __float2bfloat16(v);
    l = __float2bfloat16(v - __bfloat162float(h));
}

// SMEM tile geometry (bf16): 128 rows x 128 cols, row stride 136 elems (272 B)
#define TSTR 136
#define ROWB 272
#define GT_AHI 0
#define GT_ALO 34816
#define GT_BHI 69632
#define GT_BLO 104448
#define GT_SMEM 139264

// ---------------- K1: coordinate MLPs -> bf16 hi/lo operand matrices ----------------
__global__ __launch_bounds__(128) void k_mlp(
    const float* __restrict__ w1p, const float* __restrict__ b1p,
    const float* __restrict__ w2p, const float* __restrict__ b2p,
    const float* __restrict__ w1q, const float* __restrict__ b1q,
    const float* __restrict__ w2q, const float* __restrict__ b2q)
{
    __shared__ float sW2T[H2D * 68];
    __shared__ float sW1[2 * H1D];
    __shared__ float sB1[H1D];
    __shared__ float sB2[H2D];
    __shared__ float sTr[128 * 17];

    const bool psi = (blockIdx.y != 0);
    const float* w1 = psi ? w1q : w1p;
    const float* b1 = psi ? b1q : b1p;
    const float* w2 = psi ? w2q : w2p;
    const float* b2 = psi ? b2q : b2p;

    int t = threadIdx.x;
    for (int idx = t; idx < H1D * H2D; idx += 128) {
        int j = idx >> 7, k = idx & 127;
        sW2T[k * 68 + j] = w2[idx];
    }
    if (t < 2 * H1D) sW1[t] = w1[t];
    if (t < H1D)     sB1[t] = b1[t];
    if (t < H2D)     sB2[t] = b2[t];
    __syncthreads();

    int n0 = blockIdx.x * 128;
    int n = n0 + t;
    const float inv = 1.0f / 127.0f;
    float gx = (float)(n >> 7) * inv;
    float gy = (float)(n & 127) * inv;

    float h1[H1D];
#pragma unroll
    for (int j = 0; j < H1D; j++) {
        float v = fmaf(gx, sW1[j], fmaf(gy, sW1[H1D + j], sB1[j]));
        h1[j] = fmaxf(v, 0.0f);
    }

    if (!psi) {
        // phi: write [k][n] hi/lo, coalesced over n
        for (int k = 0; k < H2D; k++) {
            float acc = sB2[k];
            const float4* w4 = (const float4*)(&sW2T[k * 68]);
#pragma unroll
            for (int j4 = 0; j4 < 16; j4++) {
                float4 w = w4[j4];
                acc = fmaf(h1[4 * j4 + 0], w.x, acc);
                acc = fmaf(h1[4 * j4 + 1], w.y, acc);
                acc = fmaf(h1[4 * j4 + 2], w.z, acc);
                acc = fmaf(h1[4 * j4 + 3], w.w, acc);
            }
            acc = fmaxf(acc, 0.0f);
            __nv_bfloat16 h, l; split1(acc, h, l);
            g_Bphi_hi[k * NX + n] = h;
            g_Bphi_lo[k * NX + n] = l;
        }
    } else {
        // psi: chunked SMEM transpose -> [m][k] hi/lo
        for (int kc = 0; kc < 8; kc++) {
#pragma unroll
            for (int kk = 0; kk < 16; kk++) {
                int k = kc * 16 + kk;
                float acc = sB2[k];
                const float4* w4 = (const float4*)(&sW2T[k * 68]);
#pragma unroll
                for (int j4 = 0; j4 < 16; j4++) {
                    float4 w = w4[j4];
                    acc = fmaf(h1[4 * j4 + 0], w.x, acc);
                    acc = fmaf(h1[4 * j4 + 1], w.y, acc);
                    acc = fmaf(h1[4 * j4 + 2], w.z, acc);
                    acc = fmaf(h1[4 * j4 + 3], w.w, acc);
                }
                sTr[t * 17 + kk] = fmaxf(acc, 0.0f);
            }
            __syncthreads();
            for (int idx = t; idx < 2048; idx += 128) {
                int r = idx >> 4, kk = idx & 15;
                float v = sTr[r * 17 + kk];
                __nv_bfloat16 h, l; split1(v, h, l);
                size_t a = (size_t)(n0 + r) * H2D + kc * 16 + kk;
                g_Apsi_hi[a] = h;
                g_Apsi_lo[a] = l;
            }
            __syncthreads();
        }
    }
}

// ---------------- xsum[bi] = sum_n x[bi][n] ----------------
__global__ __launch_bounds__(128) void k_xsum(const float* __restrict__ x)
{
    __shared__ float sp[4];
    int row = blockIdx.x, t = threadIdx.x;
    const float4* xr = (const float4*)(x + (size_t)row * NX);
    float s = 0.0f;
    for (int j = t; j < NX / 4; j += 128) {
        float4 v = xr[j];
        s += (v.x + v.y) + (v.z + v.w);
    }
#pragma unroll
    for (int o = 16; o; o >>= 1) s += __shfl_xor_sync(0xffffffffu, s, o);
    if ((t & 31) == 0) sp[t >> 5] = s;
    __syncthreads();
    if (t == 0) g_xsum[row] = (sp[0] + sp[1]) + (sp[2] + sp[3]);
}

// ---------------- GEMM1 (mma.sync): Tpart[sp][bi][k] = x[bi,n] * phi[n->k] -----------
// grid (2 bi-tiles, 64 splits), 256 thr. Per CTA: 128 bi x 128 k, reduce 256 n (2 chunks).
__global__ __launch_bounds__(256) void k_g1(const float* __restrict__ x)
{
    extern __shared__ char dsm[];
    uint32_t sb = smem_u32(dsm);
    int t = threadIdx.x, wid = t >> 5, lane = t & 31;
    int bi0 = blockIdx.x * 128;
    int n0 = blockIdx.y * 256;
    int m_w = (wid & 3) * 32;
    int j_w = (wid >> 2) * 64;
    int lrow = lane & 15, lcol = (lane >> 4) * 8;
    int grp = lane >> 2, tig = lane & 3;

    float C[2][8][4];
#pragma unroll
    for (int a = 0; a < 2; a++)
#pragma unroll
        for (int b = 0; b < 8; b++)
#pragma unroll
            for (int d = 0; d < 4; d++) C[a][b][d] = 0.0f;

    for (int ch = 0; ch < 2; ch++) {
        int nb = n0 + ch * 128;
        // stage A from x (fp32 -> bf16 hi/lo)
        for (int idx = t; idx < 4096; idx += 256) {
            int row = idx >> 5, nq = idx & 31;
            float4 v = *(const float4*)(x + (size_t)(bi0 + row) * NX + nb + nq * 4);
            __nv_bfloat16 h0,h1,h2,h3,l0,l1,l2,l3;
            split1(v.x,h0,l0); split1(v.y,h1,l1); split1(v.z,h2,l2); split1(v.w,h3,l3);
            uint32_t off = (uint32_t)(row * ROWB + nq * 8);
            *(uint2*)(dsm + GT_AHI + off) = make_uint2(pack2(h0,h1), pack2(h2,h3));
            *(uint2*)(dsm + GT_ALO + off) = make_uint2(pack2(l0,l1), pack2(l2,l3));
        }
        // stage B from g_Bphi (bf16 copy)
        for (int idx = t; idx < 2048; idx += 256) {
            int row = idx >> 4, n8 = idx & 15;
            size_t ga = (size_t)row * NX + nb + n8 * 8;
            uint32_t off = (uint32_t)(row * ROWB + n8 * 16);
            *(uint4*)(dsm + GT_BHI + off) = *(const uint4*)(g_Bphi_hi + ga);
            *(uint4*)(dsm + GT_BLO + off) = *(const uint4*)(g_Bphi_lo + ga);
        }
        __syncthreads();

#pragma unroll
        for (int ks = 0; ks < 8; ks++) {
            int c0 = ks * 16;
            uint32_t ah[8], al[8], bh[16], bl[16];
#pragma unroll
            for (int mi = 0; mi < 2; mi++) {
                uint32_t ro = (uint32_t)(((m_w + mi * 16 + lrow) * TSTR + c0 + lcol) * 2);
                ldm4(ah + mi * 4, sb + GT_AHI + ro);
                ldm4(al + mi * 4, sb + GT_ALO + ro);
            }
#pragma unroll
            for (int q = 0; q < 4; q++) {
                uint32_t ro = (uint32_t)(((j_w + q * 16 + lrow) * TSTR + c0 + lcol) * 2);
                ldm4(bh + q * 4, sb + GT_BHI + ro);
                ldm4(bl + q * 4, sb + GT_BLO + ro);
            }
#pragma unroll
            for (int mi = 0; mi < 2; mi++)
#pragma unroll
                for (int q = 0; q < 4; q++) {
                    mma_bf16(C[mi][2*q],   ah + mi*4, bh[q*4+0], bh[q*4+2]);
                    mma_bf16(C[mi][2*q],   ah + mi*4, bl[q*4+0], bl[q*4+2]);
                    mma_bf16(C[mi][2*q],   al + mi*4, bh[q*4+0], bh[q*4+2]);
                    mma_bf16(C[mi][2*q+1], ah + mi*4, bh[q*4+1], bh[q*4+3]);
                    mma_bf16(C[mi][2*q+1], ah + mi*4, bl[q*4+1], bl[q*4+3]);
                    mma_bf16(C[mi][2*q+1], al + mi*4, bh[q*4+1], bh[q*4+3]);
                }
        }
        __syncthreads();
    }

    // write partials: [sp=by][bi][k]
#pragma unroll
    for (int mi = 0; mi < 2; mi++)
#pragma unroll
        for (int jj = 0; jj < 8; jj++) {
            int j = j_w + jj * 8 + tig * 2;
            int bi_l = m_w + mi * 16 + grp;
            size_t a0 = ((size_t)blockIdx.y * 256 + bi0 + bi_l) * 128 + j;
            *(float2*)(g_Tpart + a0)          = make_float2(C[mi][jj][0], C[mi][jj][1]);
            *(float2*)(g_Tpart + a0 + 8*128)  = make_float2(C[mi][jj][2], C[mi][jj][3]);
        }
}

// ---------------- reduce split-K -> T[bi][k] ----------------
__global__ __launch_bounds__(256) void k_reduce()
{
    int idx = blockIdx.x * 256 + threadIdx.x;   // 32768 total
    float s = 0.0f;
#pragma unroll 8
    for (int sp = 0; sp < KSPLIT; sp++)
        s += g_Tpart[(size_t)sp * (NBI * H2D) + idx];
    g_T[idx] = s;
}

// ---------------- s[b][o*32+i] ----------------
__global__ __launch_bounds__(1024) void k_s(const float* __restrict__ w3p,
                                            const float* __restrict__ b3p)
{
    __shared__ float sT[32 * 129];
    __shared__ float sXs[32];
    int b = blockIdx.x, t = threadIdx.x;
    for (int idx = t; idx < 4096; idx += 1024)
        sT[(idx >> 7) * 129 + (idx & 127)] = g_T[b * 4096 + idx];
    if (t < 32) sXs[t] = g_xsum[b * 32 + t];
    __syncthreads();
    int i = t & 31;
    float acc = b3p[t] * sXs[i];
    const float* wp = w3p + t;
#pragma unroll 4
    for (int k = 0; k < 128; k++)
        acc = fmaf(sT[i * 129 + k], wp[k * 1024], acc);
    g_S[b * 1024 + t] = acc;
}

// ---------------- U[b*32+o][k], c[b*32+o] ----------------
__global__ __launch_bounds__(256) void k_u(const float* __restrict__ w3q,
                                           const float* __restrict__ b3q)
{
    __shared__ float sW[128 * 33];
    __shared__ float sS[8 * 33];
    int o = blockIdx.x, t = threadIdx.x;
    for (int idx = t; idx < 4096; idx += 256) {
        int i = idx & 31, k = idx >> 5;
        sW[k * 33 + i] = w3q[k * 1024 + o * 32 + i];
    }
    if (t < 256) {
        int i = t & 31, bb = t >> 5;
        sS[bb * 33 + i] = g_S[bb * 1024 + o * 32 + i];
    }
    __syncthreads();
    const float inv = 1.0f / (float)NX;
    for (int idx = t; idx < 1024; idx += 256) {
        int k = idx & 127, bb = idx >> 7;
        float acc = 0.0f;
#pragma unroll
        for (int i = 0; i < 32; i++)
            acc = fmaf(sS[bb * 33 + i], sW[k * 33 + i], acc);
        g_U[(size_t)(bb * 32 + o) * 128 + k] = acc * inv;
    }
    if (t < 8) {
        float acc = 0.0f;
        for (int i = 0; i < 32; i++)
            acc = fmaf(sS[t * 33 + i], b3q[o * 32 + i], acc);
        g_c[t * 32 + o] = acc * inv;
    }
}

// ---------------- GEMM2 (mma.sync): out[bo][m] = psi[m,k] * U[bo,k] + c ----------------
// grid (128 m-tiles, 2 bo-tiles), 256 thr. K = 128 single stage.
__global__ __launch_bounds__(256) void k_g2(float* __restrict__ out)
{
    extern __shared__ char dsm[];
    __shared__ float sc[128];
    uint32_t sb = smem_u32(dsm);
    int t = threadIdx.x, wid = t >> 5, lane = t & 31;
    int m0 = blockIdx.x * 128;
    int bo0 = blockIdx.y * 128;
    int m_w = (wid & 3) * 32;
    int j_w = (wid >> 2) * 64;
    int lrow = lane & 15, lcol = (lane >> 4) * 8;
    int grp = lane >> 2, tig = lane & 3;

    if (t < 128) sc[t] = g_c[bo0 + t];

    // stage A from g_Apsi (bf16 copy), rows = m, cols = k
    for (int idx = t; idx < 2048; idx += 256) {
        int row = idx >> 4, k8 = idx & 15;
        size_t ga = (size_t)(m0 + row) * H2D + k8 * 8;
        uint32_t off = (uint32_t)(row * ROWB + k8 * 16);
        *(uint4*)(dsm + GT_AHI + off) = *(const uint4*)(g_Apsi_hi + ga);
        *(uint4*)(dsm + GT_ALO + off) = *(const uint4*)(g_Apsi_lo + ga);
    }
    // stage B from g_U (fp32 -> bf16 hi/lo), rows = bo, cols = k
    for (int idx = t; idx < 4096; idx += 256) {
        int row = idx >> 5, kq = idx & 31;
        float4 v = *(const float4*)(g_U + (size_t)(bo0 + row) * 128 + kq * 4);
        __nv_bfloat16 h0,h1,h2,h3,l0,l1,l2,l3;
        split1(v.x,h0,l0); split1(v.y,h1,l1); split1(v.z,h2,l2); split1(v.w,h3,l3);
        uint32_t off = (uint32_t)(row * ROWB + kq * 8);
        *(uint2*)(dsm + GT_BHI + off) = make_uint2(pack2(h0,h1), pack2(h2,h3));
        *(uint2*)(dsm + GT_BLO + off) = make_uint2(pack2(l0,l1), pack2(l2,l3));
    }
    __syncthreads();

    float C[2][8][4];
#pragma unroll
    for (int a = 0; a < 2; a++)
#pragma unroll
        for (int b = 0; b < 8; b++)
#pragma unroll
            for (int d = 0; d < 4; d++) C[a][b][d] = 0.0f;

#pragma unroll
    for (int ks = 0; ks < 8; ks++) {
        int c0 = ks * 16;
        uint32_t ah[8], al[8], bh[16], bl[16];
#pragma unroll
        for (int mi = 0; mi < 2; mi++) {
            uint32_t ro = (uint32_t)(((m_w + mi * 16 + lrow) * TSTR + c0 + lcol) * 2);
            ldm4(ah + mi * 4, sb + GT_AHI + ro);
            ldm4(al + mi * 4, sb + GT_ALO + ro);
        }
#pragma unroll
        for (int q = 0; q < 4; q++) {
            uint32_t ro = (uint32_t)(((j_w + q * 16 + lrow) * TSTR + c0 + lcol) * 2);
            ldm4(bh + q * 4, sb + GT_BHI + ro);
            ldm4(bl + q * 4, sb + GT_BLO + ro);
        }
#pragma unroll
        for (int mi = 0; mi < 2; mi++)
#pragma unroll
            for (int q = 0; q < 4; q++) {
                mma_bf16(C[mi][2*q],   ah + mi*4, bh[q*4+0], bh[q*4+2]);
                mma_bf16(C[mi][2*q],   ah + mi*4, bl[q*4+0], bl[q*4+2]);
                mma_bf16(C[mi][2*q],   al + mi*4, bh[q*4+0], bh[q*4+2]);
                mma_bf16(C[mi][2*q+1], ah + mi*4, bh[q*4+1], bh[q*4+3]);
                mma_bf16(C[mi][2*q+1], ah + mi*4, bl[q*4+1], bl[q*4+3]);
                mma_bf16(C[mi][2*q+1], al + mi*4, bh[q*4+1], bh[q*4+3]);
            }
    }
    __syncthreads();

    // stage D[m, bo] -> SMEM [bo][m] (pad 132), then coalesced global write over m
    float* sO = (float*)dsm;
#pragma unroll
    for (int mi = 0; mi < 2; mi++)
#pragma unroll
        for (int jj = 0; jj < 8; jj++) {
            int j = j_w + jj * 8 + tig * 2;
            int i = m_w + mi * 16 + grp;
            sO[j * 132 + i]           = C[mi][jj][0];
            sO[(j + 1) * 132 + i]     = C[mi][jj][1];
            sO[j * 132 + i + 8]       = C[mi][jj][2];
            sO[(j + 1) * 132 + i + 8] = C[mi][jj][3];
        }
    __syncthreads();
    for (int idx = t; idx < 16384; idx += 256) {
        int i = idx & 127, j = idx >> 7;
        out[(size_t)(bo0 + j) * NX + m0 + i] = sO[j * 132 + i] + sc[j];
    }
}

// ---------------- launch ----------------
extern "C" void kernel_launch(void* const* d_in, const int* in_sizes, int n_in,
                              void* d_out, int out_size)
{
    const float* x      = (const float*)d_in[0];
    const float* phi_w1 = (const float*)d_in[1];
    const float* phi_b1 = (const float*)d_in[2];
    const float* phi_w2 = (const float*)d_in[3];
    const float* phi_b2 = (const float*)d_in[4];
    const float* phi_w3 = (const float*)d_in[5];
    const float* phi_b3 = (const float*)d_in[6];
    const float* psi_w1 = (const float*)d_in[7];
    const float* psi_b1 = (const float*)d_in[8];
    const float* psi_w2 = (const float*)d_in[9];
    const float* psi_b2 = (const float*)d_in[10];
    const float* psi_w3 = (const float*)d_in[11];
    const float* psi_b3 = (const float*)d_in[12];
    float* out = (float*)d_out;

    cudaFuncSetAttribute(k_g1, cudaFuncAttributeMaxDynamicSharedMemorySize, GT_SMEM);
    cudaFuncSetAttribute(k_g2, cudaFuncAttributeMaxDynamicSharedMemorySize, GT_SMEM);

    k_mlp<<<dim3(NX / 128, 2), 128>>>(phi_w1, phi_b1, phi_w2, phi_b2,
                                      psi_w1, psi_b1, psi_w2, psi_b2);
    k_xsum<<<NBI, 128>>>(x);
    k_g1<<<dim3(2, KSPLIT), 256, GT_SMEM>>>(x);
    k_reduce<<<(NBI * H2D) / 256, 256>>>();
    k_s<<<8, 1024>>>(phi_w3, phi_b3);
    k_u<<<CO, 256>>>(psi_w3, psi_b3);
    k_g2<<<dim3(NX / 128, 2), 256, GT_SMEM>>>(out);
}

// round 6
// speedup vs baseline: 1.4894x; 1.0452x over previous
#include <cuda_runtime.h>
#include <cuda_bf16.h>
#include <cstdint>

#define NX    16384
#define CI    32
#define CO    32
#define H1D   64
#define H2D   128
#define NBI   256
#define NBO   256
#define KSPLIT 32

// ---------------- device scratch ----------------
__device__ __nv_bfloat16 g_Bphi_hi[H2D * NX];   // [k][n] phi hidden (relu'd), bf16 hi
__device__ __nv_bfloat16 g_Bphi_lo[H2D * NX];   // residual
__device__ __nv_bfloat16 g_Apsi_hi[NX * H2D];   // [m][k] psi hidden, bf16 hi
__device__ __nv_bfloat16 g_Apsi_lo[NX * H2D];
__device__ float g_Tpart[KSPLIT * NBI * H2D];   // [sp][bi][k]  4.2 MB
__device__ float g_T[NBI * H2D];                // [bi][k]
__device__ float g_xsum[NBI];
__device__ float g_S[8 * CO * CI];              // [b][o*32+i]
__device__ float g_U[NBO * H2D];                // [b*32+o][k] (scaled 1/NX)
__device__ float g_c[NBO];                      // (scaled 1/NX)

// ---------------- helpers ----------------
__device__ __forceinline__ uint32_t smem_u32(const void* p) {
    uint32_t a;
    asm("{ .reg .u64 t; cvta.to.shared.u64 t, %1; cvt.u32.u64 %0, t; }" : "=r"(a) : "l"(p));
    return a;
}
__device__ __forceinline__ void ldm4(uint32_t* r, uint32_t addr) {
    asm volatile("ldmatrix.sync.aligned.m8n8.x4.shared.b16 {%0,%1,%2,%3}, [%4];"
                 : "=r"(r[0]), "=r"(r[1]), "=r"(r[2]), "=r"(r[3]) : "r"(addr));
}
__device__ __forceinline__ void mma_bf16(float* c, const uint32_t* a, uint32_t b0, uint32_t b1) {
    asm volatile("mma.sync.aligned.m16n8k16.row.col.f32.bf16.bf16.f32 "
                 "{%0,%1,%2,%3}, {%4,%5,%6,%7}, {%8,%9}, {%0,%1,%2,%3};"
                 : "+f"(c[0]), "+f"(c[1]), "+f"(c[2]), "+f"(c[3])
                 : "r"(a[0]), "r"(a[1]), "r"(a[2]), "r"(a[3]), "r"(b0), "r"(b1));
}
__device__ __forceinline__ uint32_t pack2(__nv_bfloat16 a, __nv_bfloat16 b) {
    return (uint32_t)__bfloat16_as_ushort(a) | ((uint32_t)__bfloat16_as_ushort(b) << 16);
}
__device__ __forceinline__ void split1(float v, __nv_bfloat16& h, __nv_bfloat16& l) {
    h = __float2bfloat16(v);
    l = __float2bfloat16(v - __bfloat162float(h));
}

// SMEM tile geometry (bf16): row stride 136 elems (272 B)
#define TSTR 136
#define ROWB 272
// k_g1: A = x (64 rows), B = phi (128 rows)
#define G1_AHI 0
#define G1_ALO 17408
#define G1_BHI 34816
#define G1_BLO 69632
#define G1_SMEM 104448
// k_g2: A = psi (128 rows), B = U (64 rows)
#define G2_AHI 0
#define G2_ALO 34816
#define G2_BHI 69632
#define G2_BLO 87040
#define G2_SMEM 104448

// ---------------- K1: coordinate MLPs -> bf16 hi/lo operand matrices ----------------
__global__ __launch_bounds__(128) void k_mlp(
    const float* __restrict__ w1p, const float* __restrict__ b1p,
    const float* __restrict__ w2p, const float* __restrict__ b2p,
    const float* __restrict__ w1q, const float* __restrict__ b1q,
    const float* __restrict__ w2q, const float* __restrict__ b2q)
{
    __shared__ float sW2T[H2D * 68];
    __shared__ float sW1[2 * H1D];
    __shared__ float sB1[H1D];
    __shared__ float sB2[H2D];
    __shared__ float sTr[128 * 17];

    const bool psi = (blockIdx.y != 0);
    const float* w1 = psi ? w1q : w1p;
    const float* b1 = psi ? b1q : b1p;
    const float* w2 = psi ? w2q : w2p;
    const float* b2 = psi ? b2q : b2p;

    int t = threadIdx.x;
    for (int idx = t; idx < H1D * H2D; idx += 128) {
        int j = idx >> 7, k = idx & 127;
        sW2T[k * 68 + j] = w2[idx];
    }
    if (t < 2 * H1D) sW1[t] = w1[t];
    if (t < H1D)     sB1[t] = b1[t];
    if (t < H2D)     sB2[t] = b2[t];
    __syncthreads();

    int n0 = blockIdx.x * 128;
    int n = n0 + t;
    const float inv = 1.0f / 127.0f;
    float gx = (float)(n >> 7) * inv;
    float gy = (float)(n & 127) * inv;

    float h1[H1D];
#pragma unroll
    for (int j = 0; j < H1D; j++) {
        float v = fmaf(gx, sW1[j], fmaf(gy, sW1[H1D + j], sB1[j]));
        h1[j] = fmaxf(v, 0.0f);
    }

    if (!psi) {
        for (int k = 0; k < H2D; k++) {
            float acc = sB2[k];
            const float4* w4 = (const float4*)(&sW2T[k * 68]);
#pragma unroll
            for (int j4 = 0; j4 < 16; j4++) {
                float4 w = w4[j4];
                acc = fmaf(h1[4 * j4 + 0], w.x, acc);
                acc = fmaf(h1[4 * j4 + 1], w.y, acc);
                acc = fmaf(h1[4 * j4 + 2], w.z, acc);
                acc = fmaf(h1[4 * j4 + 3], w.w, acc);
            }
            acc = fmaxf(acc, 0.0f);
            __nv_bfloat16 h, l; split1(acc, h, l);
            g_Bphi_hi[k * NX + n] = h;
            g_Bphi_lo[k * NX + n] = l;
        }
    } else {
        for (int kc = 0; kc < 8; kc++) {
#pragma unroll
            for (int kk = 0; kk < 16; kk++) {
                int k = kc * 16 + kk;
                float acc = sB2[k];
                const float4* w4 = (const float4*)(&sW2T[k * 68]);
#pragma unroll
                for (int j4 = 0; j4 < 16; j4++) {
                    float4 w = w4[j4];
                    acc = fmaf(h1[4 * j4 + 0], w.x, acc);
                    acc = fmaf(h1[4 * j4 + 1], w.y, acc);
                    acc = fmaf(h1[4 * j4 + 2], w.z, acc);
                    acc = fmaf(h1[4 * j4 + 3], w.w, acc);
                }
                sTr[t * 17 + kk] = fmaxf(acc, 0.0f);
            }
            __syncthreads();
            for (int idx = t; idx < 2048; idx += 128) {
                int r = idx >> 4, kk = idx & 15;
                float v = sTr[r * 17 + kk];
                __nv_bfloat16 h, l; split1(v, h, l);
                size_t a = (size_t)(n0 + r) * H2D + kc * 16 + kk;
                g_Apsi_hi[a] = h;
                g_Apsi_lo[a] = l;
            }
            __syncthreads();
        }
    }
}

// ---------------- xsum[bi] = sum_n x[bi][n] ----------------
__global__ __launch_bounds__(128) void k_xsum(const float* __restrict__ x)
{
    __shared__ float sp[4];
    int row = blockIdx.x, t = threadIdx.x;
    const float4* xr = (const float4*)(x + (size_t)row * NX);
    float s = 0.0f;
    for (int j = t; j < NX / 4; j += 128) {
        float4 v = xr[j];
        s += (v.x + v.y) + (v.z + v.w);
    }
#pragma unroll
    for (int o = 16; o; o >>= 1) s += __shfl_xor_sync(0xffffffffu, s, o);
    if ((t & 31) == 0) sp[t >> 5] = s;
    __syncthreads();
    if (t == 0) g_xsum[row] = (sp[0] + sp[1]) + (sp[2] + sp[3]);
}

// ---------------- GEMM1 (mma.sync): Tpart[sp][bi][k] = x[bi,n] * phi[n->k] -----------
// grid (4 bi-tiles of 64, 32 splits), 256 thr. Per CTA: 64 bi x 128 k, 512 n (4 chunks).
__global__ __launch_bounds__(256, 2) void k_g1(const float* __restrict__ x)
{
    extern __shared__ char dsm[];
    uint32_t sb = smem_u32(dsm);
    int t = threadIdx.x, wid = t >> 5, lane = t & 31;
    int bi0 = blockIdx.x * 64;
    int n0 = blockIdx.y * 512;
    int m_w = (wid & 1) * 32;
    int j_w = (wid >> 1) * 32;
    int lrow = lane & 15, lcol = (lane >> 4) * 8;
    int grp = lane >> 2, tig = lane & 3;

    float C[2][4][4];
#pragma unroll
    for (int a = 0; a < 2; a++)
#pragma unroll
        for (int b = 0; b < 4; b++)
#pragma unroll
            for (int d = 0; d < 4; d++) C[a][b][d] = 0.0f;

    for (int ch = 0; ch < 4; ch++) {
        int nb = n0 + ch * 128;
        // stage A from x (64 rows, fp32 -> bf16 hi/lo)
        for (int idx = t; idx < 2048; idx += 256) {
            int row = idx >> 5, nq = idx & 31;
            float4 v = *(const float4*)(x + (size_t)(bi0 + row) * NX + nb + nq * 4);
            __nv_bfloat16 h0,h1,h2,h3,l0,l1,l2,l3;
            split1(v.x,h0,l0); split1(v.y,h1,l1); split1(v.z,h2,l2); split1(v.w,h3,l3);
            uint32_t off = (uint32_t)(row * ROWB + nq * 8);
            *(uint2*)(dsm + G1_AHI + off) = make_uint2(pack2(h0,h1), pack2(h2,h3));
            *(uint2*)(dsm + G1_ALO + off) = make_uint2(pack2(l0,l1), pack2(l2,l3));
        }
        // stage B from g_Bphi (128 rows, bf16 copy)
        for (int idx = t; idx < 2048; idx += 256) {
            int row = idx >> 4, n8 = idx & 15;
            size_t ga = (size_t)row * NX + nb + n8 * 8;
            uint32_t off = (uint32_t)(row * ROWB + n8 * 16);
            *(uint4*)(dsm + G1_BHI + off) = *(const uint4*)(g_Bphi_hi + ga);
            *(uint4*)(dsm + G1_BLO + off) = *(const uint4*)(g_Bphi_lo + ga);
        }
        __syncthreads();

#pragma unroll
        for (int ks = 0; ks < 8; ks++) {
            int c0 = ks * 16;
            uint32_t ah[8], al[8], bh[8], bl[8];
#pragma unroll
            for (int mi = 0; mi < 2; mi++) {
                uint32_t ro = (uint32_t)(((m_w + mi * 16 + lrow) * TSTR + c0 + lcol) * 2);
                ldm4(ah + mi * 4, sb + G1_AHI + ro);
                ldm4(al + mi * 4, sb + G1_ALO + ro);
            }
#pragma unroll
            for (int q = 0; q < 2; q++) {
                uint32_t ro = (uint32_t)(((j_w + q * 16 + lrow) * TSTR + c0 + lcol) * 2);
                ldm4(bh + q * 4, sb + G1_BHI + ro);
                ldm4(bl + q * 4, sb + G1_BLO + ro);
            }
#pragma unroll
            for (int mi = 0; mi < 2; mi++)
#pragma unroll
                for (int q = 0; q < 2; q++) {
                    mma_bf16(C[mi][2*q],   ah + mi*4, bh[q*4+0], bh[q*4+2]);
                    mma_bf16(C[mi][2*q],   ah + mi*4, bl[q*4+0], bl[q*4+2]);
                    mma_bf16(C[mi][2*q],   al + mi*4, bh[q*4+0], bh[q*4+2]);
                    mma_bf16(C[mi][2*q+1], ah + mi*4, bh[q*4+1], bh[q*4+3]);
                    mma_bf16(C[mi][2*q+1], ah + mi*4, bl[q*4+1], bl[q*4+3]);
                    mma_bf16(C[mi][2*q+1], al + mi*4, bh[q*4+1], bh[q*4+3]);
                }
        }
        __syncthreads();
    }

    // write partials: [sp=by][bi][k]
#pragma unroll
    for (int mi = 0; mi < 2; mi++)
#pragma unroll
        for (int jj = 0; jj < 4; jj++) {
            int j = j_w + jj * 8 + tig * 2;
            int bi_l = m_w + mi * 16 + grp;
            size_t a0 = ((size_t)blockIdx.y * 256 + bi0 + bi_l) * 128 + j;
            *(float2*)(g_Tpart + a0)          = make_float2(C[mi][jj][0], C[mi][jj][1]);
            *(float2*)(g_Tpart + a0 + 8*128)  = make_float2(C[mi][jj][2], C[mi][jj][3]);
        }
}

// ---------------- reduce split-K -> T[bi][k]  (2-way parallel, deterministic) --------
__global__ __launch_bounds__(256) void k_reduce()
{
    __shared__ float sm[4][32];
    int t = threadIdx.x, b = blockIdx.x;       // grid 256
    int warp = t >> 5, lane = t & 31;
    int p = warp & 1;
    int og = b * 4 + (warp >> 1);              // 0..1023
    int o = og * 32 + lane;                    // output index 0..32767
    float s = 0.0f;
#pragma unroll
    for (int sp = 0; sp < 16; sp++)
        s += g_Tpart[(size_t)(p * 16 + sp) * (NBI * H2D) + o];
    if (p) sm[warp >> 1][lane] = s;
    __syncthreads();
    if (!p) g_T[o] = s + sm[warp >> 1][lane];
}

// ---------------- s[b][o*32+i] ----------------
__global__ __launch_bounds__(1024) void k_s(const float* __restrict__ w3p,
                                            const float* __restrict__ b3p)
{
    __shared__ float sT[32 * 129];
    __shared__ float sXs[32];
    int b = blockIdx.x, t = threadIdx.x;
    for (int idx = t; idx < 4096; idx += 1024)
        sT[(idx >> 7) * 129 + (idx & 127)] = g_T[b * 4096 + idx];
    if (t < 32) sXs[t] = g_xsum[b * 32 + t];
    __syncthreads();
    int i = t & 31;
    float acc = b3p[t] * sXs[i];
    const float* wp = w3p + t;
#pragma unroll 4
    for (int k = 0; k < 128; k++)
        acc = fmaf(sT[i * 129 + k], wp[k * 1024], acc);
    g_S[b * 1024 + t] = acc;
}

// ---------------- U[b*32+o][k], c[b*32+o] ----------------
__global__ __launch_bounds__(256) void k_u(const float* __restrict__ w3q,
                                           const float* __restrict__ b3q)
{
    __shared__ float sW[128 * 33];
    __shared__ float sS[8 * 33];
    int o = blockIdx.x, t = threadIdx.x;
    for (int idx = t; idx < 4096; idx += 256) {
        int i = idx & 31, k = idx >> 5;
        sW[k * 33 + i] = w3q[k * 1024 + o * 32 + i];
    }
    if (t < 256) {
        int i = t & 31, bb = t >> 5;
        sS[bb * 33 + i] = g_S[bb * 1024 + o * 32 + i];
    }
    __syncthreads();
    const float inv = 1.0f / (float)NX;
    for (int idx = t; idx < 1024; idx += 256) {
        int k = idx & 127, bb = idx >> 7;
        float acc = 0.0f;
#pragma unroll
        for (int i = 0; i < 32; i++)
            acc = fmaf(sS[bb * 33 + i], sW[k * 33 + i], acc);
        g_U[(size_t)(bb * 32 + o) * 128 + k] = acc * inv;
    }
    if (t < 8) {
        float acc = 0.0f;
        for (int i = 0; i < 32; i++)
            acc = fmaf(sS[t * 33 + i], b3q[o * 32 + i], acc);
        g_c[t * 32 + o] = acc * inv;
    }
}

// ---------------- GEMM2 (mma.sync): out[bo][m] = psi[m,k] * U[bo,k] + c ----------------
// grid (128 m-tiles, 4 bo-tiles of 64), 256 thr. K = 128 single stage.
__global__ __launch_bounds__(256, 2) void k_g2(float* __restrict__ out)
{
    extern __shared__ char dsm[];
    __shared__ float sc[64];
    uint32_t sb = smem_u32(dsm);
    int t = threadIdx.x, wid = t >> 5, lane = t & 31;
    int m0 = blockIdx.x * 128;
    int bo0 = blockIdx.y * 64;
    int m_w = (wid & 3) * 32;
    int j_w = (wid >> 2) * 32;
    int lrow = lane & 15, lcol = (lane >> 4) * 8;
    int grp = lane >> 2, tig = lane & 3;

    if (t < 64) sc[t] = g_c[bo0 + t];

    // stage A from g_Apsi (128 rows m x 128 k, bf16 copy)
    for (int idx = t; idx < 2048; idx += 256) {
        int row = idx >> 4, k8 = idx & 15;
        size_t ga = (size_t)(m0 + row) * H2D + k8 * 8;
        uint32_t off = (uint32_t)(row * ROWB + k8 * 16);
        *(uint4*)(dsm + G2_AHI + off) = *(const uint4*)(g_Apsi_hi + ga);
        *(uint4*)(dsm + G2_ALO + off) = *(const uint4*)(g_Apsi_lo + ga);
    }
    // stage B from g_U (64 rows bo x 128 k, fp32 -> bf16 hi/lo)
    for (int idx = t; idx < 2048; idx += 256) {
        int row = idx >> 5, kq = idx & 31;
        float4 v = *(const float4*)(g_U + (size_t)(bo0 + row) * 128 + kq * 4);
        __nv_bfloat16 h0,h1,h2,h3,l0,l1,l2,l3;
        split1(v.x,h0,l0); split1(v.y,h1,l1); split1(v.z,h2,l2); split1(v.w,h3,l3);
        uint32_t off = (uint32_t)(row * ROWB + kq * 8);
        *(uint2*)(dsm + G2_BHI + off) = make_uint2(pack2(h0,h1), pack2(h2,h3));
        *(uint2*)(dsm + G2_BLO + off) = make_uint2(pack2(l0,l1), pack2(l2,l3));
    }
    __syncthreads();

    float C[2][4][4];
#pragma unroll
    for (int a = 0; a < 2; a++)
#pragma unroll
        for (int b = 0; b < 4; b++)
#pragma unroll
            for (int d = 0; d < 4; d++) C[a][b][d] = 0.0f;

#pragma unroll
    for (int ks = 0; ks < 8; ks++) {
        int c0 = ks * 16;
        uint32_t ah[8], al[8], bh[8], bl[8];
#pragma unroll
        for (int mi = 0; mi < 2; mi++) {
            uint32_t ro = (uint32_t)(((m_w + mi * 16 + lrow) * TSTR + c0 + lcol) * 2);
            ldm4(ah + mi * 4, sb + G2_AHI + ro);
            ldm4(al + mi * 4, sb + G2_ALO + ro);
        }
#pragma unroll
        for (int q = 0; q < 2; q++) {
            uint32_t ro = (uint32_t)(((j_w + q * 16 + lrow) * TSTR + c0 + lcol) * 2);
            ldm4(bh + q * 4, sb + G2_BHI + ro);
            ldm4(bl + q * 4, sb + G2_BLO + ro);
        }
#pragma unroll
        for (int mi = 0; mi < 2; mi++)
#pragma unroll
            for (int q = 0; q < 2; q++) {
                mma_bf16(C[mi][2*q],   ah + mi*4, bh[q*4+0], bh[q*4+2]);
                mma_bf16(C[mi][2*q],   ah + mi*4, bl[q*4+0], bl[q*4+2]);
                mma_bf16(C[mi][2*q],   al + mi*4, bh[q*4+0], bh[q*4+2]);
                mma_bf16(C[mi][2*q+1], ah + mi*4, bh[q*4+1], bh[q*4+3]);
                mma_bf16(C[mi][2*q+1], ah + mi*4, bl[q*4+1], bl[q*4+3]);
                mma_bf16(C[mi][2*q+1], al + mi*4, bh[q*4+1], bh[q*4+3]);
            }
    }
    __syncthreads();

    // stage D[m, bo] -> SMEM [bo][m] (pad 132), then coalesced global write over m
    float* sO = (float*)dsm;
#pragma unroll
    for (int mi = 0; mi < 2; mi++)
#pragma unroll
        for (int jj = 0; jj < 4; jj++) {
            int j = j_w + jj * 8 + tig * 2;
            int i = m_w + mi * 16 + grp;
            sO[j * 132 + i]           = C[mi][jj][0];
            sO[(j + 1) * 132 + i]     = C[mi][jj][1];
            sO[j * 132 + i + 8]       = C[mi][jj][2];
            sO[(j + 1) * 132 + i + 8] = C[mi][jj][3];
        }
    __syncthreads();
    for (int idx = t; idx < 8192; idx += 256) {
        int i = idx & 127, j = idx >> 7;
        out[(size_t)(bo0 + j) * NX + m0 + i] = sO[j * 132 + i] + sc[j];
    }
}

// ---------------- launch ----------------
extern "C" void kernel_launch(void* const* d_in, const int* in_sizes, int n_in,
                              void* d_out, int out_size)
{
    const float* x      = (const float*)d_in[0];
    const float* phi_w1 = (const float*)d_in[1];
    const float* phi_b1 = (const float*)d_in[2];
    const float* phi_w2 = (const float*)d_in[3];
    const float* phi_b2 = (const float*)d_in[4];
    const float* phi_w3 = (const float*)d_in[5];
    const float* phi_b3 = (const float*)d_in[6];
    const float* psi_w1 = (const float*)d_in[7];
    const float* psi_b1 = (const float*)d_in[8];
    const float* psi_w2 = (const float*)d_in[9];
    const float* psi_b2 = (const float*)d_in[10];
    const float* psi_w3 = (const float*)d_in[11];
    const float* psi_b3 = (const float*)d_in[12];
    float* out = (float*)d_out;

    cudaFuncSetAttribute(k_g1, cudaFuncAttributeMaxDynamicSharedMemorySize, G1_SMEM);
    cudaFuncSetAttribute(k_g2, cudaFuncAttributeMaxDynamicSharedMemorySize, G2_SMEM);

    k_mlp<<<dim3(NX / 128, 2), 128>>>(phi_w1, phi_b1, phi_w2, phi_b2,
                                      psi_w1, psi_b1, psi_w2, psi_b2);
    k_xsum<<<NBI, 128>>>(x);
    k_g1<<<dim3(4, KSPLIT), 256, G1_SMEM>>>(x);
    k_reduce<<<256, 256>>>();
    k_s<<<8, 1024>>>(phi_w3, phi_b3);
    k_u<<<CO, 256>>>(psi_w3, psi_b3);
    k_g2<<<dim3(NX / 128, 4), 256, G2_SMEM>>>(out);
}

// round 7
// speedup vs baseline: 1.8421x; 1.2368x over previous
#include <cuda_runtime.h>
#include <cuda_bf16.h>
#include <cstdint>

#define NX    16384
#define CI    32
#define CO    32
#define H1D   64
#define H2D   128
#define NBI   256
#define NBO   256
#define KSPLIT 32

// ---------------- device scratch ----------------
__device__ __nv_bfloat16 g_Bphi_hi[H2D * NX];   // [k][n] phi hidden (relu'd), bf16 hi
__device__ __nv_bfloat16 g_Bphi_lo[H2D * NX];   // residual
__device__ __nv_bfloat16 g_Apsi_hi[NX * H2D];   // [m][k] psi hidden, bf16 hi
__device__ __nv_bfloat16 g_Apsi_lo[NX * H2D];
__device__ float g_Tpart[KSPLIT * NBI * H2D];   // [sp][bi][k]  4.2 MB
__device__ float g_T[NBI * H2D];                // [bi][k]
__device__ float g_xsum[NBI];
__device__ float g_S[8 * CO * CI];              // [b][o*32+i]
__device__ float g_U[NBO * H2D];                // [b*32+o][k] (scaled 1/NX)
__device__ float g_c[NBO];                      // (scaled 1/NX)

// ---------------- helpers ----------------
__device__ __forceinline__ uint32_t smem_u32(const void* p) {
    uint32_t a;
    asm("{ .reg .u64 t; cvta.to.shared.u64 t, %1; cvt.u32.u64 %0, t; }" : "=r"(a) : "l"(p));
    return a;
}
__device__ __forceinline__ void ldm4(uint32_t* r, uint32_t addr) {
    asm volatile("ldmatrix.sync.aligned.m8n8.x4.shared.b16 {%0,%1,%2,%3}, [%4];"
                 : "=r"(r[0]), "=r"(r[1]), "=r"(r[2]), "=r"(r[3]) : "r"(addr));
}
__device__ __forceinline__ void mma_bf16(float* c, const uint32_t* a, uint32_t b0, uint32_t b1) {
    asm volatile("mma.sync.aligned.m16n8k16.row.col.f32.bf16.bf16.f32 "
                 "{%0,%1,%2,%3}, {%4,%5,%6,%7}, {%8,%9}, {%0,%1,%2,%3};"
                 : "+f"(c[0]), "+f"(c[1]), "+f"(c[2]), "+f"(c[3])
                 : "r"(a[0]), "r"(a[1]), "r"(a[2]), "r"(a[3]), "r"(b0), "r"(b1));
}
__device__ __forceinline__ uint32_t pack2(__nv_bfloat16 a, __nv_bfloat16 b) {
    return (uint32_t)__bfloat16_as_ushort(a) | ((uint32_t)__bfloat16_as_ushort(b) << 16);
}
__device__ __forceinline__ void split1(float v, __nv_bfloat16& h, __nv_bfloat16& l) {
    h = __float2bfloat16(v);
    l = __float2bfloat16(v - __bfloat162float(h));
}

// SMEM tile geometry for GEMM1/2 (bf16): row stride 136 elems (272 B)
#define TSTR 136
#define ROWB 272
// k_g1: A = x (64 rows), B = phi (128 rows)
#define G1_AHI 0
#define G1_ALO 17408
#define G1_BHI 34816
#define G1_BLO 69632
#define G1_SMEM 104448
// k_g2: A = psi (128 rows), B = U (64 rows)
#define G2_AHI 0
#define G2_ALO 34816
#define G2_BHI 69632
#define G2_BLO 87040
#define G2_SMEM 104448
// k_mlp: A = h1 (128 n x 64 j), B = w2T (128 k x 64 j), stride 72 elems (144 B)
#define MSTR 72
#define M_AHI 0
#define M_ALO 18432
#define M_BHI 36864
#define M_BLO 55296
#define MLP_SMEM 73728

// ---------------- K1: coordinate MLPs, layer2 on tensor pipe ----------------
// grid (128, 2), 256 thr. Per block: 128 n-points -> h1 SIMT, h2 = h1 @ w2 via mma.
__global__ __launch_bounds__(256) void k_mlp(
    const float* __restrict__ w1p, const float* __restrict__ b1p,
    const float* __restrict__ w2p, const float* __restrict__ b2p,
    const float* __restrict__ w1q, const float* __restrict__ b1q,
    const float* __restrict__ w2q, const float* __restrict__ b2q)
{
    extern __shared__ char dsm[];
    __shared__ float sW1[2 * H1D];
    __shared__ float sB1[H1D];
    __shared__ float sB2[H2D];
    uint32_t sb = smem_u32(dsm);

    const bool psi = (blockIdx.y != 0);
    const float* w1 = psi ? w1q : w1p;
    const float* b1 = psi ? b1q : b1p;
    const float* w2 = psi ? w2q : w2p;
    const float* b2 = psi ? b2q : b2p;

    int t = threadIdx.x, wid = t >> 5, lane = t & 31;
    int n0 = blockIdx.x * 128;

    if (t < 2 * H1D) sW1[t] = w1[t];
    if (t < H1D)     sB1[t] = b1[t];
    if (t < H2D)     sB2[t] = b2[t];

    // stage w2^T hi/lo: [k][j], reduction j contiguous (coalesced global read over k)
    for (int idx = t; idx < H1D * H2D; idx += 256) {
        int k = idx & 127, j = idx >> 7;
        float v = w2[j * 128 + k];
        __nv_bfloat16 h, l; split1(v, h, l);
        uint32_t off = (uint32_t)((k * MSTR + j) * 2);
        *(__nv_bfloat16*)(dsm + M_BHI + off) = h;
        *(__nv_bfloat16*)(dsm + M_BLO + off) = l;
    }
    __syncthreads();

    // h1 = relu(g @ w1 + b1) -> A tiles hi/lo. Thread: one n, half of j.
    {
        int nl = t >> 1;
        int n = n0 + nl;
        int j0 = (t & 1) * 32;
        const float inv = 1.0f / 127.0f;
        float gx = (float)(n >> 7) * inv;
        float gy = (float)(n & 127) * inv;
#pragma unroll
        for (int jj = 0; jj < 32; jj += 2) {
            int j = j0 + jj;
            float v0 = fmaxf(fmaf(gx, sW1[j],     fmaf(gy, sW1[H1D + j],     sB1[j])),     0.0f);
            float v1 = fmaxf(fmaf(gx, sW1[j + 1], fmaf(gy, sW1[H1D + j + 1], sB1[j + 1])), 0.0f);
            __nv_bfloat16 h0, l0, h1v, l1; split1(v0, h0, l0); split1(v1, h1v, l1);
            uint32_t off = (uint32_t)((nl * MSTR + j) * 2);
            *(uint32_t*)(dsm + M_AHI + off) = pack2(h0, h1v);
            *(uint32_t*)(dsm + M_ALO + off) = pack2(l0, l1);
        }
    }
    __syncthreads();

    // mma: D[128 n][128 k] = A[128 n][64 j] * B[128 k][64 j]^T, 3-pass hi/lo
    int m_w = (wid & 3) * 32;
    int j_w = (wid >> 2) * 64;
    int lrow = lane & 15, lcol = (lane >> 4) * 8;
    int grp = lane >> 2, tig = lane & 3;

    float C[2][8][4];
#pragma unroll
    for (int a = 0; a < 2; a++)
#pragma unroll
        for (int b = 0; b < 8; b++)
#pragma unroll
            for (int d = 0; d < 4; d++) C[a][b][d] = 0.0f;

#pragma unroll
    for (int ks = 0; ks < 4; ks++) {
        int c0 = ks * 16;
        uint32_t ah[8], al[8], bh[16], bl[16];
#pragma unroll
        for (int mi = 0; mi < 2; mi++) {
            uint32_t ro = (uint32_t)(((m_w + mi * 16 + lrow) * MSTR + c0 + lcol) * 2);
            ldm4(ah + mi * 4, sb + M_AHI + ro);
            ldm4(al + mi * 4, sb + M_ALO + ro);
        }
#pragma unroll
        for (int q = 0; q < 4; q++) {
            uint32_t ro = (uint32_t)(((j_w + q * 16 + lrow) * MSTR + c0 + lcol) * 2);
            ldm4(bh + q * 4, sb + M_BHI + ro);
            ldm4(bl + q * 4, sb + M_BLO + ro);
        }
#pragma unroll
        for (int mi = 0; mi < 2; mi++)
#pragma unroll
            for (int q = 0; q < 4; q++) {
                mma_bf16(C[mi][2*q],   ah + mi*4, bh[q*4+0], bh[q*4+2]);
                mma_bf16(C[mi][2*q],   ah + mi*4, bl[q*4+0], bl[q*4+2]);
                mma_bf16(C[mi][2*q],   al + mi*4, bh[q*4+0], bh[q*4+2]);
                mma_bf16(C[mi][2*q+1], ah + mi*4, bh[q*4+1], bh[q*4+3]);
                mma_bf16(C[mi][2*q+1], ah + mi*4, bl[q*4+1], bl[q*4+3]);
                mma_bf16(C[mi][2*q+1], al + mi*4, bh[q*4+1], bh[q*4+3]);
            }
    }
    __syncthreads();

    // stage D[n][k] to SMEM (stride 133, conflict-free both ways), overwrites A/B tiles
    float* sO = (float*)dsm;
#pragma unroll
    for (int mi = 0; mi < 2; mi++)
#pragma unroll
        for (int jj = 0; jj < 8; jj++) {
            int j = j_w + jj * 8 + tig * 2;
            int i = m_w + mi * 16 + grp;
            sO[i * 133 + j]           = C[mi][jj][0];
            sO[i * 133 + j + 1]       = C[mi][jj][1];
            sO[(i + 8) * 133 + j]     = C[mi][jj][2];
            sO[(i + 8) * 133 + j + 1] = C[mi][jj][3];
        }
    __syncthreads();

    // epilogue: +b2, relu, hi/lo split, write in GEMM-native layout
    if (!psi) {
        for (int idx = t; idx < 16384; idx += 256) {
            int k = idx >> 7, r = idx & 127;
            float v = fmaxf(sO[r * 133 + k] + sB2[k], 0.0f);
            __nv_bfloat16 h, l; split1(v, h, l);
            size_t a = (size_t)k * NX + n0 + r;       // coalesced over r
            g_Bphi_hi[a] = h;
            g_Bphi_lo[a] = l;
        }
    } else {
        for (int idx = t; idx < 16384; idx += 256) {
            int row = idx >> 7, k = idx & 127;
            float v = fmaxf(sO[row * 133 + k] + sB2[k], 0.0f);
            __nv_bfloat16 h, l; split1(v, h, l);
            size_t a = (size_t)(n0 + row) * H2D + k;  // coalesced over k
            g_Apsi_hi[a] = h;
            g_Apsi_lo[a] = l;
        }
    }
}

// ---------------- xsum[bi] = sum_n x[bi][n] ----------------
__global__ __launch_bounds__(128) void k_xsum(const float* __restrict__ x)
{
    __shared__ float sp[4];
    int row = blockIdx.x, t = threadIdx.x;
    const float4* xr = (const float4*)(x + (size_t)row * NX);
    float s = 0.0f;
    for (int j = t; j < NX / 4; j += 128) {
        float4 v = xr[j];
        s += (v.x + v.y) + (v.z + v.w);
    }
#pragma unroll
    for (int o = 16; o; o >>= 1) s += __shfl_xor_sync(0xffffffffu, s, o);
    if ((t & 31) == 0) sp[t >> 5] = s;
    __syncthreads();
    if (t == 0) g_xsum[row] = (sp[0] + sp[1]) + (sp[2] + sp[3]);
}

// ---------------- GEMM1 (mma.sync): Tpart[sp][bi][k] = x[bi,n] * phi[n->k] -----------
__global__ __launch_bounds__(256, 2) void k_g1(const float* __restrict__ x)
{
    extern __shared__ char dsm[];
    uint32_t sb = smem_u32(dsm);
    int t = threadIdx.x, wid = t >> 5, lane = t & 31;
    int bi0 = blockIdx.x * 64;
    int n0 = blockIdx.y * 512;
    int m_w = (wid & 1) * 32;
    int j_w = (wid >> 1) * 32;
    int lrow = lane & 15, lcol = (lane >> 4) * 8;
    int grp = lane >> 2, tig = lane & 3;

    float C[2][4][4];
#pragma unroll
    for (int a = 0; a < 2; a++)
#pragma unroll
        for (int b = 0; b < 4; b++)
#pragma unroll
            for (int d = 0; d < 4; d++) C[a][b][d] = 0.0f;

    for (int ch = 0; ch < 4; ch++) {
        int nb = n0 + ch * 128;
        for (int idx = t; idx < 2048; idx += 256) {
            int row = idx >> 5, nq = idx & 31;
            float4 v = *(const float4*)(x + (size_t)(bi0 + row) * NX + nb + nq * 4);
            __nv_bfloat16 h0,h1,h2,h3,l0,l1,l2,l3;
            split1(v.x,h0,l0); split1(v.y,h1,l1); split1(v.z,h2,l2); split1(v.w,h3,l3);
            uint32_t off = (uint32_t)(row * ROWB + nq * 8);
            *(uint2*)(dsm + G1_AHI + off) = make_uint2(pack2(h0,h1), pack2(h2,h3));
            *(uint2*)(dsm + G1_ALO + off) = make_uint2(pack2(l0,l1), pack2(l2,l3));
        }
        for (int idx = t; idx < 2048; idx += 256) {
            int row = idx >> 4, n8 = idx & 15;
            size_t ga = (size_t)row * NX + nb + n8 * 8;
            uint32_t off = (uint32_t)(row * ROWB + n8 * 16);
            *(uint4*)(dsm + G1_BHI + off) = *(const uint4*)(g_Bphi_hi + ga);
            *(uint4*)(dsm + G1_BLO + off) = *(const uint4*)(g_Bphi_lo + ga);
        }
        __syncthreads();

#pragma unroll
        for (int ks = 0; ks < 8; ks++) {
            int c0 = ks * 16;
            uint32_t ah[8], al[8], bh[8], bl[8];
#pragma unroll
            for (int mi = 0; mi < 2; mi++) {
                uint32_t ro = (uint32_t)(((m_w + mi * 16 + lrow) * TSTR + c0 + lcol) * 2);
                ldm4(ah + mi * 4, sb + G1_AHI + ro);
                ldm4(al + mi * 4, sb + G1_ALO + ro);
            }
#pragma unroll
            for (int q = 0; q < 2; q++) {
                uint32_t ro = (uint32_t)(((j_w + q * 16 + lrow) * TSTR + c0 + lcol) * 2);
                ldm4(bh + q * 4, sb + G1_BHI + ro);
                ldm4(bl + q * 4, sb + G1_BLO + ro);
            }
#pragma unroll
            for (int mi = 0; mi < 2; mi++)
#pragma unroll
                for (int q = 0; q < 2; q++) {
                    mma_bf16(C[mi][2*q],   ah + mi*4, bh[q*4+0], bh[q*4+2]);
                    mma_bf16(C[mi][2*q],   ah + mi*4, bl[q*4+0], bl[q*4+2]);
                    mma_bf16(C[mi][2*q],   al + mi*4, bh[q*4+0], bh[q*4+2]);
                    mma_bf16(C[mi][2*q+1], ah + mi*4, bh[q*4+1], bh[q*4+3]);
                    mma_bf16(C[mi][2*q+1], ah + mi*4, bl[q*4+1], bl[q*4+3]);
                    mma_bf16(C[mi][2*q+1], al + mi*4, bh[q*4+1], bh[q*4+3]);
                }
        }
        __syncthreads();
    }

#pragma unroll
    for (int mi = 0; mi < 2; mi++)
#pragma unroll
        for (int jj = 0; jj < 4; jj++) {
            int j = j_w + jj * 8 + tig * 2;
            int bi_l = m_w + mi * 16 + grp;
            size_t a0 = ((size_t)blockIdx.y * 256 + bi0 + bi_l) * 128 + j;
            *(float2*)(g_Tpart + a0)          = make_float2(C[mi][jj][0], C[mi][jj][1]);
            *(float2*)(g_Tpart + a0 + 8*128)  = make_float2(C[mi][jj][2], C[mi][jj][3]);
        }
}

// ---------------- reduce split-K -> T[bi][k]  (4-way parallel, deterministic) --------
__global__ __launch_bounds__(256) void k_reduce()
{
    __shared__ float sm[2][4][32];
    int t = threadIdx.x, b = blockIdx.x;       // grid 512
    int warp = t >> 5, lane = t & 31;
    int p = warp & 3;                          // 4-way split over sp
    int g = warp >> 2;                         // 2 outputs groups per block
    int o = (b * 2 + g) * 32 + lane;           // output index 0..32767
    float s = 0.0f;
#pragma unroll
    for (int sp = 0; sp < 8; sp++)
        s += g_Tpart[(size_t)(p * 8 + sp) * (NBI * H2D) + o];
    sm[g][p][lane] = s;
    __syncthreads();
    if (p == 0)
        g_T[o] = (sm[g][0][lane] + sm[g][1][lane]) + (sm[g][2][lane] + sm[g][3][lane]);
}

// ---------------- s[b][o*32+i] ----------------
__global__ __launch_bounds__(1024) void k_s(const float* __restrict__ w3p,
                                            const float* __restrict__ b3p)
{
    __shared__ float sT[32 * 129];
    __shared__ float sXs[32];
    int b = blockIdx.x, t = threadIdx.x;
    for (int idx = t; idx < 4096; idx += 1024)
        sT[(idx >> 7) * 129 + (idx & 127)] = g_T[b * 4096 + idx];
    if (t < 32) sXs[t] = g_xsum[b * 32 + t];
    __syncthreads();
    int i = t & 31;
    float acc = b3p[t] * sXs[i];
    const float* wp = w3p + t;
#pragma unroll 4
    for (int k = 0; k < 128; k++)
        acc = fmaf(sT[i * 129 + k], wp[k * 1024], acc);
    g_S[b * 1024 + t] = acc;
}

// ---------------- U[b*32+o][k], c[b*32+o] ----------------
__global__ __launch_bounds__(256) void k_u(const float* __restrict__ w3q,
                                           const float* __restrict__ b3q)
{
    __shared__ float sW[128 * 33];
    __shared__ float sS[8 * 33];
    int o = blockIdx.x, t = threadIdx.x;
    for (int idx = t; idx < 4096; idx += 256) {
        int i = idx & 31, k = idx >> 5;
        sW[k * 33 + i] = w3q[k * 1024 + o * 32 + i];
    }
    if (t < 256) {
        int i = t & 31, bb = t >> 5;
        sS[bb * 33 + i] = g_S[bb * 1024 + o * 32 + i];
    }
    __syncthreads();
    const float inv = 1.0f / (float)NX;
    for (int idx = t; idx < 1024; idx += 256) {
        int k = idx & 127, bb = idx >> 7;
        float acc = 0.0f;
#pragma unroll
        for (int i = 0; i < 32; i++)
            acc = fmaf(sS[bb * 33 + i], sW[k * 33 + i], acc);
        g_U[(size_t)(bb * 32 + o) * 128 + k] = acc * inv;
    }
    if (t < 8) {
        float acc = 0.0f;
        for (int i = 0; i < 32; i++)
            acc = fmaf(sS[t * 33 + i], b3q[o * 32 + i], acc);
        g_c[t * 32 + o] = acc * inv;
    }
}

// ---------------- GEMM2 (mma.sync): out[bo][m] = psi[m,k] * U[bo,k] + c ----------------
__global__ __launch_bounds__(256, 2) void k_g2(float* __restrict__ out)
{
    extern __shared__ char dsm[];
    __shared__ float sc[64];
    uint32_t sb = smem_u32(dsm);
    int t = threadIdx.x, wid = t >> 5, lane = t & 31;
    int m0 = blockIdx.x * 128;
    int bo0 = blockIdx.y * 64;
    int m_w = (wid & 3) * 32;
    int j_w = (wid >> 2) * 32;
    int lrow = lane & 15, lcol = (lane >> 4) * 8;
    int grp = lane >> 2, tig = lane & 3;

    if (t < 64) sc[t] = g_c[bo0 + t];

    for (int idx = t; idx < 2048; idx += 256) {
        int row = idx >> 4, k8 = idx & 15;
        size_t ga = (size_t)(m0 + row) * H2D + k8 * 8;
        uint32_t off = (uint32_t)(row * ROWB + k8 * 16);
        *(uint4*)(dsm + G2_AHI + off) = *(const uint4*)(g_Apsi_hi + ga);
        *(uint4*)(dsm + G2_ALO + off) = *(const uint4*)(g_Apsi_lo + ga);
    }
    for (int idx = t; idx < 2048; idx += 256) {
        int row = idx >> 5, kq = idx & 31;
        float4 v = *(const float4*)(g_U + (size_t)(bo0 + row) * 128 + kq * 4);
        __nv_bfloat16 h0,h1,h2,h3,l0,l1,l2,l3;
        split1(v.x,h0,l0); split1(v.y,h1,l1); split1(v.z,h2,l2); split1(v.w,h3,l3);
        uint32_t off = (uint32_t)(row * ROWB + kq * 8);
        *(uint2*)(dsm + G2_BHI + off) = make_uint2(pack2(h0,h1), pack2(h2,h3));
        *(uint2*)(dsm + G2_BLO + off) = make_uint2(pack2(l0,l1), pack2(l2,l3));
    }
    __syncthreads();

    float C[2][4][4];
#pragma unroll
    for (int a = 0; a < 2; a++)
#pragma unroll
        for (int b = 0; b < 4; b++)
#pragma unroll
            for (int d = 0; d < 4; d++) C[a][b][d] = 0.0f;

#pragma unroll
    for (int ks = 0; ks < 8; ks++) {
        int c0 = ks * 16;
        uint32_t ah[8], al[8], bh[8], bl[8];
#pragma unroll
        for (int mi = 0; mi < 2; mi++) {
            uint32_t ro = (uint32_t)(((m_w + mi * 16 + lrow) * TSTR + c0 + lcol) * 2);
            ldm4(ah + mi * 4, sb + G2_AHI + ro);
            ldm4(al + mi * 4, sb + G2_ALO + ro);
        }
#pragma unroll
        for (int q = 0; q < 2; q++) {
            uint32_t ro = (uint32_t)(((j_w + q * 16 + lrow) * TSTR + c0 + lcol) * 2);
            ldm4(bh + q * 4, sb + G2_BHI + ro);
            ldm4(bl + q * 4, sb + G2_BLO + ro);
        }
#pragma unroll
        for (int mi = 0; mi < 2; mi++)
#pragma unroll
            for (int q = 0; q < 2; q++) {
                mma_bf16(C[mi][2*q],   ah + mi*4, bh[q*4+0], bh[q*4+2]);
                mma_bf16(C[mi][2*q],   ah + mi*4, bl[q*4+0], bl[q*4+2]);
                mma_bf16(C[mi][2*q],   al + mi*4, bh[q*4+0], bh[q*4+2]);
                mma_bf16(C[mi][2*q+1], ah + mi*4, bh[q*4+1], bh[q*4+3]);
                mma_bf16(C[mi][2*q+1], ah + mi*4, bl[q*4+1], bl[q*4+3]);
                mma_bf16(C[mi][2*q+1], al + mi*4, bh[q*4+1], bh[q*4+3]);
            }
    }
    __syncthreads();

    float* sO = (float*)dsm;
#pragma unroll
    for (int mi = 0; mi < 2; mi++)
#pragma unroll
        for (int jj = 0; jj < 4; jj++) {
            int j = j_w + jj * 8 + tig * 2;
            int i = m_w + mi * 16 + grp;
            sO[j * 132 + i]           = C[mi][jj][0];
            sO[(j + 1) * 132 + i]     = C[mi][jj][1];
            sO[j * 132 + i + 8]       = C[mi][jj][2];
            sO[(j + 1) * 132 + i + 8] = C[mi][jj][3];
        }
    __syncthreads();
    for (int idx = t; idx < 8192; idx += 256) {
        int i = idx & 127, j = idx >> 7;
        out[(size_t)(bo0 + j) * NX + m0 + i] = sO[j * 132 + i] + sc[j];
    }
}

// ---------------- launch ----------------
extern "C" void kernel_launch(void* const* d_in, const int* in_sizes, int n_in,
                              void* d_out, int out_size)
{
    const float* x      = (const float*)d_in[0];
    const float* phi_w1 = (const float*)d_in[1];
    const float* phi_b1 = (const float*)d_in[2];
    const float* phi_w2 = (const float*)d_in[3];
    const float* phi_b2 = (const float*)d_in[4];
    const float* phi_w3 = (const float*)d_in[5];
    const float* phi_b3 = (const float*)d_in[6];
    const float* psi_w1 = (const float*)d_in[7];
    const float* psi_b1 = (const float*)d_in[8];
    const float* psi_w2 = (const float*)d_in[9];
    const float* psi_b2 = (const float*)d_in[10];
    const float* psi_w3 = (const float*)d_in[11];
    const float* psi_b3 = (const float*)d_in[12];
    float* out = (float*)d_out;

    cudaFuncSetAttribute(k_mlp, cudaFuncAttributeMaxDynamicSharedMemorySize, MLP_SMEM);
    cudaFuncSetAttribute(k_g1,  cudaFuncAttributeMaxDynamicSharedMemorySize, G1_SMEM);
    cudaFuncSetAttribute(k_g2,  cudaFuncAttributeMaxDynamicSharedMemorySize, G2_SMEM);

    k_mlp<<<dim3(NX / 128, 2), 256, MLP_SMEM>>>(phi_w1, phi_b1, phi_w2, phi_b2,
                                                psi_w1, psi_b1, psi_w2, psi_b2);
    k_xsum<<<NBI, 128>>>(x);
    k_g1<<<dim3(4, KSPLIT), 256, G1_SMEM>>>(x);
    k_reduce<<<512, 256>>>();
    k_s<<<8, 1024>>>(phi_w3, phi_b3);
    k_u<<<CO, 256>>>(psi_w3, psi_b3);
    k_g2<<<dim3(NX / 128, 4), 256, G2_SMEM>>>(out);
}

// round 8
// speedup vs baseline: 1.8911x; 1.0266x over previous
#include <cuda_runtime.h>
#include <cuda_bf16.h>
#include <cstdint>

#define NX    16384
#define CI    32
#define CO    32
#define H1D   64
#define H2D   128
#define NBI   256
#define NBO   256
#define KSPLIT 32

// ---------------- device scratch ----------------
__device__ __nv_bfloat16 g_Bphi_hi[H2D * NX];   // [k][n] phi hidden (relu'd), bf16 hi
__device__ __nv_bfloat16 g_Bphi_lo[H2D * NX];   // residual
__device__ __nv_bfloat16 g_Apsi_hi[NX * H2D];   // [m][k] psi hidden, bf16 hi
__device__ __nv_bfloat16 g_Apsi_lo[NX * H2D];
__device__ float g_Tpart[KSPLIT * NBI * H2D];   // [sp][bi][k]  4.2 MB
__device__ float g_xsumpart[KSPLIT * NBI];      // [sp][bi]
__device__ float g_T[NBI * H2D];                // [bi][k]
__device__ float g_xsum[NBI];
__device__ float g_U[NBO * H2D];                // [b*32+o][k] (scaled 1/NX)
__device__ float g_c[NBO];                      // (scaled 1/NX)

// ---------------- helpers ----------------
__device__ __forceinline__ uint32_t smem_u32(const void* p) {
    uint32_t a;
    asm("{ .reg .u64 t; cvta.to.shared.u64 t, %1; cvt.u32.u64 %0, t; }" : "=r"(a) : "l"(p));
    return a;
}
__device__ __forceinline__ void ldm4(uint32_t* r, uint32_t addr) {
    asm volatile("ldmatrix.sync.aligned.m8n8.x4.shared.b16 {%0,%1,%2,%3}, [%4];"
                 : "=r"(r[0]), "=r"(r[1]), "=r"(r[2]), "=r"(r[3]) : "r"(addr));
}
__device__ __forceinline__ void mma_bf16(float* c, const uint32_t* a, uint32_t b0, uint32_t b1) {
    asm volatile("mma.sync.aligned.m16n8k16.row.col.f32.bf16.bf16.f32 "
                 "{%0,%1,%2,%3}, {%4,%5,%6,%7}, {%8,%9}, {%0,%1,%2,%3};"
                 : "+f"(c[0]), "+f"(c[1]), "+f"(c[2]), "+f"(c[3])
                 : "r"(a[0]), "r"(a[1]), "r"(a[2]), "r"(a[3]), "r"(b0), "r"(b1));
}
__device__ __forceinline__ uint32_t pack2(__nv_bfloat16 a, __nv_bfloat16 b) {
    return (uint32_t)__bfloat16_as_ushort(a) | ((uint32_t)__bfloat16_as_ushort(b) << 16);
}
__device__ __forceinline__ void split1(float v, __nv_bfloat16& h, __nv_bfloat16& l) {
    h = __float2bfloat16(v);
    l = __float2bfloat16(v - __bfloat162float(h));
}

// SMEM tile geometry for GEMM1/2 (bf16): row stride 136 elems (272 B)
#define TSTR 136
#define ROWB 272
// k_g1: A = x (64 rows), B = phi (128 rows)
#define G1_AHI 0
#define G1_ALO 17408
#define G1_BHI 34816
#define G1_BLO 69632
#define G1_SMEM 104448
// k_g2: A = psi (128 rows), B = U (64 rows)
#define G2_AHI 0
#define G2_ALO 34816
#define G2_BHI 69632
#define G2_BLO 87040
#define G2_SMEM 104448
// k_mlp: A = h1 (128 n x 64 j), B = w2T (128 k x 64 j), stride 72 elems (144 B)
#define MSTR 72
#define M_AHI 0
#define M_ALO 18432
#define M_BHI 36864
#define M_BLO 55296
#define MLP_SMEM 73728
// k_su offsets
#define SU_ST 0
#define SU_WP 132096
#define SU_WQ 148992
#define SU_SS 165888
#define SU_XS 166912
#define SU_SMEM 167936

// ---------------- K1: coordinate MLPs, layer2 on tensor pipe ----------------
__global__ __launch_bounds__(256) void k_mlp(
    const float* __restrict__ w1p, const float* __restrict__ b1p,
    const float* __restrict__ w2p, const float* __restrict__ b2p,
    const float* __restrict__ w1q, const float* __restrict__ b1q,
    const float* __restrict__ w2q, const float* __restrict__ b2q)
{
    extern __shared__ char dsm[];
    __shared__ float sW1[2 * H1D];
    __shared__ float sB1[H1D];
    __shared__ float sB2[H2D];
    uint32_t sb = smem_u32(dsm);

    const bool psi = (blockIdx.y != 0);
    const float* w1 = psi ? w1q : w1p;
    const float* b1 = psi ? b1q : b1p;
    const float* w2 = psi ? w2q : w2p;
    const float* b2 = psi ? b2q : b2p;

    int t = threadIdx.x, wid = t >> 5, lane = t & 31;
    int n0 = blockIdx.x * 128;

    if (t < 2 * H1D) sW1[t] = w1[t];
    if (t < H1D)     sB1[t] = b1[t];
    if (t < H2D)     sB2[t] = b2[t];

    for (int idx = t; idx < H1D * H2D; idx += 256) {
        int k = idx & 127, j = idx >> 7;
        float v = w2[j * 128 + k];
        __nv_bfloat16 h, l; split1(v, h, l);
        uint32_t off = (uint32_t)((k * MSTR + j) * 2);
        *(__nv_bfloat16*)(dsm + M_BHI + off) = h;
        *(__nv_bfloat16*)(dsm + M_BLO + off) = l;
    }
    __syncthreads();

    {
        int nl = t >> 1;
        int n = n0 + nl;
        int j0 = (t & 1) * 32;
        const float inv = 1.0f / 127.0f;
        float gx = (float)(n >> 7) * inv;
        float gy = (float)(n & 127) * inv;
#pragma unroll
        for (int jj = 0; jj < 32; jj += 2) {
            int j = j0 + jj;
            float v0 = fmaxf(fmaf(gx, sW1[j],     fmaf(gy, sW1[H1D + j],     sB1[j])),     0.0f);
            float v1 = fmaxf(fmaf(gx, sW1[j + 1], fmaf(gy, sW1[H1D + j + 1], sB1[j + 1])), 0.0f);
            __nv_bfloat16 h0, l0, h1v, l1; split1(v0, h0, l0); split1(v1, h1v, l1);
            uint32_t off = (uint32_t)((nl * MSTR + j) * 2);
            *(uint32_t*)(dsm + M_AHI + off) = pack2(h0, h1v);
            *(uint32_t*)(dsm + M_ALO + off) = pack2(l0, l1);
        }
    }
    __syncthreads();

    int m_w = (wid & 3) * 32;
    int j_w = (wid >> 2) * 64;
    int lrow = lane & 15, lcol = (lane >> 4) * 8;
    int grp = lane >> 2, tig = lane & 3;

    float C[2][8][4];
#pragma unroll
    for (int a = 0; a < 2; a++)
#pragma unroll
        for (int b = 0; b < 8; b++)
#pragma unroll
            for (int d = 0; d < 4; d++) C[a][b][d] = 0.0f;

#pragma unroll
    for (int ks = 0; ks < 4; ks++) {
        int c0 = ks * 16;
        uint32_t ah[8], al[8], bh[16], bl[16];
#pragma unroll
        for (int mi = 0; mi < 2; mi++) {
            uint32_t ro = (uint32_t)(((m_w + mi * 16 + lrow) * MSTR + c0 + lcol) * 2);
            ldm4(ah + mi * 4, sb + M_AHI + ro);
            ldm4(al + mi * 4, sb + M_ALO + ro);
        }
#pragma unroll
        for (int q = 0; q < 4; q++) {
            uint32_t ro = (uint32_t)(((j_w + q * 16 + lrow) * MSTR + c0 + lcol) * 2);
            ldm4(bh + q * 4, sb + M_BHI + ro);
            ldm4(bl + q * 4, sb + M_BLO + ro);
        }
#pragma unroll
        for (int mi = 0; mi < 2; mi++)
#pragma unroll
            for (int q = 0; q < 4; q++) {
                mma_bf16(C[mi][2*q],   ah + mi*4, bh[q*4+0], bh[q*4+2]);
                mma_bf16(C[mi][2*q],   ah + mi*4, bl[q*4+0], bl[q*4+2]);
                mma_bf16(C[mi][2*q],   al + mi*4, bh[q*4+0], bh[q*4+2]);
                mma_bf16(C[mi][2*q+1], ah + mi*4, bh[q*4+1], bh[q*4+3]);
                mma_bf16(C[mi][2*q+1], ah + mi*4, bl[q*4+1], bl[q*4+3]);
                mma_bf16(C[mi][2*q+1], al + mi*4, bh[q*4+1], bh[q*4+3]);
            }
    }
    __syncthreads();

    float* sO = (float*)dsm;
#pragma unroll
    for (int mi = 0; mi < 2; mi++)
#pragma unroll
        for (int jj = 0; jj < 8; jj++) {
            int j = j_w + jj * 8 + tig * 2;
            int i = m_w + mi * 16 + grp;
            sO[i * 133 + j]           = C[mi][jj][0];
            sO[i * 133 + j + 1]       = C[mi][jj][1];
            sO[(i + 8) * 133 + j]     = C[mi][jj][2];
            sO[(i + 8) * 133 + j + 1] = C[mi][jj][3];
        }
    __syncthreads();

    if (!psi) {
        for (int idx = t; idx < 16384; idx += 256) {
            int k = idx >> 7, r = idx & 127;
            float v = fmaxf(sO[r * 133 + k] + sB2[k], 0.0f);
            __nv_bfloat16 h, l; split1(v, h, l);
            size_t a = (size_t)k * NX + n0 + r;
            g_Bphi_hi[a] = h;
            g_Bphi_lo[a] = l;
        }
    } else {
        for (int idx = t; idx < 16384; idx += 256) {
            int row = idx >> 7, k = idx & 127;
            float v = fmaxf(sO[row * 133 + k] + sB2[k], 0.0f);
            __nv_bfloat16 h, l; split1(v, h, l);
            size_t a = (size_t)(n0 + row) * H2D + k;
            g_Apsi_hi[a] = h;
            g_Apsi_lo[a] = l;
        }
    }
}

// ---------------- GEMM1 (mma.sync) + fused xsum partials -----------------------------
// grid (4 bi-tiles of 64, 32 splits), 256 thr. Per CTA: 64 bi x 128 k, 512 n (4 chunks).
__global__ __launch_bounds__(256, 2) void k_g1(const float* __restrict__ x)
{
    extern __shared__ char dsm[];
    uint32_t sb = smem_u32(dsm);
    int t = threadIdx.x, wid = t >> 5, lane = t & 31;
    int bi0 = blockIdx.x * 64;
    int n0 = blockIdx.y * 512;
    int m_w = (wid & 1) * 32;
    int j_w = (wid >> 1) * 32;
    int lrow = lane & 15, lcol = (lane >> 4) * 8;
    int grp = lane >> 2, tig = lane & 3;

    float C[2][4][4];
#pragma unroll
    for (int a = 0; a < 2; a++)
#pragma unroll
        for (int b = 0; b < 4; b++)
#pragma unroll
            for (int d = 0; d < 4; d++) C[a][b][d] = 0.0f;

    float xs[8];
#pragma unroll
    for (int i = 0; i < 8; i++) xs[i] = 0.0f;

    for (int ch = 0; ch < 4; ch++) {
        int nb = n0 + ch * 128;
        // stage A from x (64 rows, fp32 -> bf16 hi/lo) + xsum accumulation
#pragma unroll
        for (int it = 0; it < 8; it++) {
            int idx = t + it * 256;
            int row = idx >> 5, nq = idx & 31;
            float4 v = *(const float4*)(x + (size_t)(bi0 + row) * NX + nb + nq * 4);
            xs[it] += (v.x + v.y) + (v.z + v.w);
            __nv_bfloat16 h0,h1,h2,h3,l0,l1,l2,l3;
            split1(v.x,h0,l0); split1(v.y,h1,l1); split1(v.z,h2,l2); split1(v.w,h3,l3);
            uint32_t off = (uint32_t)(row * ROWB + nq * 8);
            *(uint2*)(dsm + G1_AHI + off) = make_uint2(pack2(h0,h1), pack2(h2,h3));
            *(uint2*)(dsm + G1_ALO + off) = make_uint2(pack2(l0,l1), pack2(l2,l3));
        }
        // stage B from g_Bphi (128 rows, bf16 copy)
        for (int idx = t; idx < 2048; idx += 256) {
            int row = idx >> 4, n8 = idx & 15;
            size_t ga = (size_t)row * NX + nb + n8 * 8;
            uint32_t off = (uint32_t)(row * ROWB + n8 * 16);
            *(uint4*)(dsm + G1_BHI + off) = *(const uint4*)(g_Bphi_hi + ga);
            *(uint4*)(dsm + G1_BLO + off) = *(const uint4*)(g_Bphi_lo + ga);
        }
        __syncthreads();

#pragma unroll
        for (int ks = 0; ks < 8; ks++) {
            int c0 = ks * 16;
            uint32_t ah[8], al[8], bh[8], bl[8];
#pragma unroll
            for (int mi = 0; mi < 2; mi++) {
                uint32_t ro = (uint32_t)(((m_w + mi * 16 + lrow) * TSTR + c0 + lcol) * 2);
                ldm4(ah + mi * 4, sb + G1_AHI + ro);
                ldm4(al + mi * 4, sb + G1_ALO + ro);
            }
#pragma unroll
            for (int q = 0; q < 2; q++) {
                uint32_t ro = (uint32_t)(((j_w + q * 16 + lrow) * TSTR + c0 + lcol) * 2);
                ldm4(bh + q * 4, sb + G1_BHI + ro);
                ldm4(bl + q * 4, sb + G1_BLO + ro);
            }
#pragma unroll
            for (int mi = 0; mi < 2; mi++)
#pragma unroll
                for (int q = 0; q < 2; q++) {
                    mma_bf16(C[mi][2*q],   ah + mi*4, bh[q*4+0], bh[q*4+2]);
                    mma_bf16(C[mi][2*q],   ah + mi*4, bl[q*4+0], bl[q*4+2]);
                    mma_bf16(C[mi][2*q],   al + mi*4, bh[q*4+0], bh[q*4+2]);
                    mma_bf16(C[mi][2*q+1], ah + mi*4, bh[q*4+1], bh[q*4+3]);
                    mma_bf16(C[mi][2*q+1], ah + mi*4, bl[q*4+1], bl[q*4+3]);
                    mma_bf16(C[mi][2*q+1], al + mi*4, bh[q*4+1], bh[q*4+3]);
                }
        }
        __syncthreads();
    }

    // write T partials: [sp=by][bi][k]
#pragma unroll
    for (int mi = 0; mi < 2; mi++)
#pragma unroll
        for (int jj = 0; jj < 4; jj++) {
            int j = j_w + jj * 8 + tig * 2;
            int bi_l = m_w + mi * 16 + grp;
            size_t a0 = ((size_t)blockIdx.y * 256 + bi0 + bi_l) * 128 + j;
            *(float2*)(g_Tpart + a0)          = make_float2(C[mi][jj][0], C[mi][jj][1]);
            *(float2*)(g_Tpart + a0 + 8*128)  = make_float2(C[mi][jj][2], C[mi][jj][3]);
        }

    // xsum partials: warp wid owns rows wid + 8*i (lane = n-quad within row)
#pragma unroll
    for (int i = 0; i < 8; i++) {
        float v = xs[i];
#pragma unroll
        for (int o = 16; o; o >>= 1) v += __shfl_xor_sync(0xffffffffu, v, o);
        if (lane == 0)
            g_xsumpart[blockIdx.y * 256 + bi0 + wid + 8 * i] = v;
    }
}

// ---------------- reduce split-K -> T[bi][k] + xsum (deterministic) ------------------
__global__ __launch_bounds__(256) void k_reduce()
{
    __shared__ float sm[8][32];
    int t = threadIdx.x, b = blockIdx.x;       // grid 1024
    int p = t >> 5, lane = t & 31;
    int o = b * 32 + lane;                     // output 0..32767
    float s = 0.0f;
#pragma unroll
    for (int sp = 0; sp < 4; sp++)
        s += g_Tpart[(size_t)(p * 4 + sp) * (NBI * H2D) + o];
    sm[p][lane] = s;
    __syncthreads();
    if (p == 0) {
        float r = ((sm[0][lane] + sm[1][lane]) + (sm[2][lane] + sm[3][lane]))
                + ((sm[4][lane] + sm[5][lane]) + (sm[6][lane] + sm[7][lane]));
        g_T[o] = r;
    }
    if (b < 8 && p == 1) {                     // xsum final reduce (256 outputs)
        int o2 = b * 32 + lane;
        float xsv = 0.0f;
#pragma unroll
        for (int sp = 0; sp < KSPLIT; sp++) xsv += g_xsumpart[sp * 256 + o2];
        g_xsum[o2] = xsv;
    }
}

// ---------------- k_su: s + U + c fused (grid 32, one block per o) ----------------
__global__ __launch_bounds__(256) void k_su(
    const float* __restrict__ w3p, const float* __restrict__ b3p,
    const float* __restrict__ w3q, const float* __restrict__ b3q)
{
    extern __shared__ char dsm[];
    float* sT  = (float*)(dsm + SU_ST);    // [bi][k] stride 129
    float* sWp = (float*)(dsm + SU_WP);    // [k][i]  stride 33
    float* sWq = (float*)(dsm + SU_WQ);
    float* sS  = (float*)(dsm + SU_SS);    // [b*32+i]
    float* sXs = (float*)(dsm + SU_XS);
    int o = blockIdx.x, t = threadIdx.x;

    for (int idx = t; idx < NBI * H2D; idx += 256)
        sT[(idx >> 7) * 129 + (idx & 127)] = g_T[idx];
    for (int idx = t; idx < 4096; idx += 256) {
        int i = idx & 31, k = idx >> 5;
        sWp[k * 33 + i] = w3p[k * 1024 + o * 32 + i];
        sWq[k * 33 + i] = w3q[k * 1024 + o * 32 + i];
    }
    sXs[t] = g_xsum[t];
    __syncthreads();

    {   // s[b][o*32+i], thread t = b*32+i
        int i = t & 31;
        float acc = b3p[o * 32 + i] * sXs[t];
#pragma unroll 4
        for (int k = 0; k < 128; k++)
            acc = fmaf(sT[t * 129 + k], sWp[k * 33 + i], acc);
        sS[t] = acc;
    }
    __syncthreads();

    const float inv = 1.0f / (float)NX;
    for (int idx = t; idx < 1024; idx += 256) {
        int k = idx & 127, bb = idx >> 7;
        float u = 0.0f;
#pragma unroll
        for (int ii = 0; ii < 32; ii++)
            u = fmaf(sS[bb * 32 + ii], sWq[k * 33 + ii], u);
        g_U[(size_t)(bb * 32 + o) * 128 + k] = u * inv;
    }
    if (t < 8) {
        float cc = 0.0f;
        for (int ii = 0; ii < 32; ii++)
            cc = fmaf(sS[t * 32 + ii], b3q[o * 32 + ii], cc);
        g_c[t * 32 + o] = cc * inv;
    }
}

// ---------------- GEMM2 (mma.sync): out[bo][m] = psi[m,k] * U[bo,k] + c ----------------
__global__ __launch_bounds__(256, 2) void k_g2(float* __restrict__ out)
{
    extern __shared__ char dsm[];
    __shared__ float sc[64];
    uint32_t sb = smem_u32(dsm);
    int t = threadIdx.x, wid = t >> 5, lane = t & 31;
    int m0 = blockIdx.x * 128;
    int bo0 = blockIdx.y * 64;
    int m_w = (wid & 3) * 32;
    int j_w = (wid >> 2) * 32;
    int lrow = lane & 15, lcol = (lane >> 4) * 8;
    int grp = lane >> 2, tig = lane & 3;

    if (t < 64) sc[t] = g_c[bo0 + t];

    for (int idx = t; idx < 2048; idx += 256) {
        int row = idx >> 4, k8 = idx & 15;
        size_t ga = (size_t)(m0 + row) * H2D + k8 * 8;
        uint32_t off = (uint32_t)(row * ROWB + k8 * 16);
        *(uint4*)(dsm + G2_AHI + off) = *(const uint4*)(g_Apsi_hi + ga);
        *(uint4*)(dsm + G2_ALO + off) = *(const uint4*)(g_Apsi_lo + ga);
    }
    for (int idx = t; idx < 2048; idx += 256) {
        int row = idx >> 5, kq = idx & 31;
        float4 v = *(const float4*)(g_U + (size_t)(bo0 + row) * 128 + kq * 4);
        __nv_bfloat16 h0,h1,h2,h3,l0,l1,l2,l3;
        split1(v.x,h0,l0); split1(v.y,h1,l1); split1(v.z,h2,l2); split1(v.w,h3,l3);
        uint32_t off = (uint32_t)(row * ROWB + kq * 8);
        *(uint2*)(dsm + G2_BHI + off) = make_uint2(pack2(h0,h1), pack2(h2,h3));
        *(uint2*)(dsm + G2_BLO + off) = make_uint2(pack2(l0,l1), pack2(l2,l3));
    }
    __syncthreads();

    float C[2][4][4];
#pragma unroll
    for (int a = 0; a < 2; a++)
#pragma unroll
        for (int b = 0; b < 4; b++)
#pragma unroll
            for (int d = 0; d < 4; d++) C[a][b][d] = 0.0f;

#pragma unroll
    for (int ks = 0; ks < 8; ks++) {
        int c0 = ks * 16;
        uint32_t ah[8], al[8], bh[8], bl[8];
#pragma unroll
        for (int mi = 0; mi < 2; mi++) {
            uint32_t ro = (uint32_t)(((m_w + mi * 16 + lrow) * TSTR + c0 + lcol) * 2);
            ldm4(ah + mi * 4, sb + G2_AHI + ro);
            ldm4(al + mi * 4, sb + G2_ALO + ro);
        }
#pragma unroll
        for (int q = 0; q < 2; q++) {
            uint32_t ro = (uint32_t)(((j_w + q * 16 + lrow) * TSTR + c0 + lcol) * 2);
            ldm4(bh + q * 4, sb + G2_BHI + ro);
            ldm4(bl + q * 4, sb + G2_BLO + ro);
        }
#pragma unroll
        for (int mi = 0; mi < 2; mi++)
#pragma unroll
            for (int q = 0; q < 2; q++) {
                mma_bf16(C[mi][2*q],   ah + mi*4, bh[q*4+0], bh[q*4+2]);
                mma_bf16(C[mi][2*q],   ah + mi*4, bl[q*4+0], bl[q*4+2]);
                mma_bf16(C[mi][2*q],   al + mi*4, bh[q*4+0], bh[q*4+2]);
                mma_bf16(C[mi][2*q+1], ah + mi*4, bh[q*4+1], bh[q*4+3]);
                mma_bf16(C[mi][2*q+1], ah + mi*4, bl[q*4+1], bl[q*4+3]);
                mma_bf16(C[mi][2*q+1], al + mi*4, bh[q*4+1], bh[q*4+3]);
            }
    }
    __syncthreads();

    float* sO = (float*)dsm;
#pragma unroll
    for (int mi = 0; mi < 2; mi++)
#pragma unroll
        for (int jj = 0; jj < 4; jj++) {
            int j = j_w + jj * 8 + tig * 2;
            int i = m_w + mi * 16 + grp;
            sO[j * 132 + i]           = C[mi][jj][0];
            sO[(j + 1) * 132 + i]     = C[mi][jj][1];
            sO[j * 132 + i + 8]       = C[mi][jj][2];
            sO[(j + 1) * 132 + i + 8] = C[mi][jj][3];
        }
    __syncthreads();
    for (int idx = t; idx < 8192; idx += 256) {
        int i = idx & 127, j = idx >> 7;
        out[(size_t)(bo0 + j) * NX + m0 + i] = sO[j * 132 + i] + sc[j];
    }
}

// ---------------- launch ----------------
extern "C" void kernel_launch(void* const* d_in, const int* in_sizes, int n_in,
                              void* d_out, int out_size)
{
    const float* x      = (const float*)d_in[0];
    const float* phi_w1 = (const float*)d_in[1];
    const float* phi_b1 = (const float*)d_in[2];
    const float* phi_w2 = (const float*)d_in[3];
    const float* phi_b2 = (const float*)d_in[4];
    const float* phi_w3 = (const float*)d_in[5];
    const float* phi_b3 = (const float*)d_in[6];
    const float* psi_w1 = (const float*)d_in[7];
    const float* psi_b1 = (const float*)d_in[8];
    const float* psi_w2 = (const float*)d_in[9];
    const float* psi_b2 = (const float*)d_in[10];
    const float* psi_w3 = (const float*)d_in[11];
    const float* psi_b3 = (const float*)d_in[12];
    float* out = (float*)d_out;

    cudaFuncSetAttribute(k_mlp, cudaFuncAttributeMaxDynamicSharedMemorySize, MLP_SMEM);
    cudaFuncSetAttribute(k_g1,  cudaFuncAttributeMaxDynamicSharedMemorySize, G1_SMEM);
    cudaFuncSetAttribute(k_su,  cudaFuncAttributeMaxDynamicSharedMemorySize, SU_SMEM);
    cudaFuncSetAttribute(k_g2,  cudaFuncAttributeMaxDynamicSharedMemorySize, G2_SMEM);

    k_mlp<<<dim3(NX / 128, 2), 256, MLP_SMEM>>>(phi_w1, phi_b1, phi_w2, phi_b2,
                                                psi_w1, psi_b1, psi_w2, psi_b2);
    k_g1<<<dim3(4, KSPLIT), 256, G1_SMEM>>>(x);
    k_reduce<<<1024, 256>>>();
    k_su<<<CO, 256, SU_SMEM>>>(phi_w3, phi_b3, psi_w3, psi_b3);
    k_g2<<<dim3(NX / 128, 4), 256, G2_SMEM>>>(out);
}

// round 9
// speedup vs baseline: 1.9991x; 1.0571x over previous
#include <cuda_runtime.h>
#include <cuda_bf16.h>
#include <cstdint>

#define NX    16384
#define CI    32
#define CO    32
#define H1D   64
#define H2D   128
#define NBI   256
#define NBO   256
#define KSPLIT 32

// ---------------- device scratch ----------------
__device__ __nv_bfloat16 g_Bphi_hi[H2D * NX];   // [k][n] phi hidden (relu'd), bf16 hi
__device__ __nv_bfloat16 g_Bphi_lo[H2D * NX];   // residual
__device__ __nv_bfloat16 g_Apsi_hi[NX * H2D];   // [m][k] psi hidden, bf16 hi
__device__ __nv_bfloat16 g_Apsi_lo[NX * H2D];
__device__ float g_Tpart[KSPLIT * NBI * H2D];   // [sp][bi][k]  4.2 MB
__device__ float g_xsumpart[KSPLIT * NBI];      // [sp][bi]
__device__ float g_T[NBI * H2D];                // [bi][k]
__device__ float g_xsum[NBI];
__device__ float g_S[8 * CO * CI];              // [b][o*32+i]
__device__ float g_U[NBO * H2D];                // [b*32+o][k] (scaled 1/NX)
__device__ float g_c[NBO];                      // (scaled 1/NX)

// ---------------- helpers ----------------
__device__ __forceinline__ uint32_t smem_u32(const void* p) {
    uint32_t a;
    asm("{ .reg .u64 t; cvta.to.shared.u64 t, %1; cvt.u32.u64 %0, t; }" : "=r"(a) : "l"(p));
    return a;
}
__device__ __forceinline__ void ldm4(uint32_t* r, uint32_t addr) {
    asm volatile("ldmatrix.sync.aligned.m8n8.x4.shared.b16 {%0,%1,%2,%3}, [%4];"
                 : "=r"(r[0]), "=r"(r[1]), "=r"(r[2]), "=r"(r[3]) : "r"(addr));
}
__device__ __forceinline__ void mma_bf16(float* c, const uint32_t* a, uint32_t b0, uint32_t b1) {
    asm volatile("mma.sync.aligned.m16n8k16.row.col.f32.bf16.bf16.f32 "
                 "{%0,%1,%2,%3}, {%4,%5,%6,%7}, {%8,%9}, {%0,%1,%2,%3};"
                 : "+f"(c[0]), "+f"(c[1]), "+f"(c[2]), "+f"(c[3])
                 : "r"(a[0]), "r"(a[1]), "r"(a[2]), "r"(a[3]), "r"(b0), "r"(b1));
}
__device__ __forceinline__ uint32_t pack2(__nv_bfloat16 a, __nv_bfloat16 b) {
    return (uint32_t)__bfloat16_as_ushort(a) | ((uint32_t)__bfloat16_as_ushort(b) << 16);
}
__device__ __forceinline__ void split1(float v, __nv_bfloat16& h, __nv_bfloat16& l) {
    h = __float2bfloat16(v);
    l = __float2bfloat16(v - __bfloat162float(h));
}

// SMEM tile geometry for GEMM1/2 (bf16): row stride 136 elems (272 B)
#define TSTR 136
#define ROWB 272
// k_g1: A = x (64 rows), B = phi (128 rows)
#define G1_AHI 0
#define G1_ALO 17408
#define G1_BHI 34816
#define G1_BLO 69632
#define G1_SMEM 104448
// k_g2: A = psi (128 rows), B = U (64 rows)
#define G2_AHI 0
#define G2_ALO 34816
#define G2_BHI 69632
#define G2_BLO 87040
#define G2_SMEM 104448
// k_mlp: A = h1 (128 n x 64 j), B = w2T (128 k x 64 j), stride 72 elems (144 B)
#define MSTR 72
#define M_AHI 0
#define M_ALO 18432
#define M_BHI 36864
#define M_BLO 55296
#define MLP_SMEM 73728

// ---------------- K1: coordinate MLPs, layer2 on tensor pipe ----------------
__global__ __launch_bounds__(256) void k_mlp(
    const float* __restrict__ w1p, const float* __restrict__ b1p,
    const float* __restrict__ w2p, const float* __restrict__ b2p,
    const float* __restrict__ w1q, const float* __restrict__ b1q,
    const float* __restrict__ w2q, const float* __restrict__ b2q)
{
    extern __shared__ char dsm[];
    __shared__ float sW1[2 * H1D];
    __shared__ float sB1[H1D];
    __shared__ float sB2[H2D];
    uint32_t sb = smem_u32(dsm);

    const bool psi = (blockIdx.y != 0);
    const float* w1 = psi ? w1q : w1p;
    const float* b1 = psi ? b1q : b1p;
    const float* w2 = psi ? w2q : w2p;
    const float* b2 = psi ? b2q : b2p;

    int t = threadIdx.x, wid = t >> 5, lane = t & 31;
    int n0 = blockIdx.x * 128;

    if (t < 2 * H1D) sW1[t] = w1[t];
    if (t < H1D)     sB1[t] = b1[t];
    if (t < H2D)     sB2[t] = b2[t];

    for (int idx = t; idx < H1D * H2D; idx += 256) {
        int k = idx & 127, j = idx >> 7;
        float v = w2[j * 128 + k];
        __nv_bfloat16 h, l; split1(v, h, l);
        uint32_t off = (uint32_t)((k * MSTR + j) * 2);
        *(__nv_bfloat16*)(dsm + M_BHI + off) = h;
        *(__nv_bfloat16*)(dsm + M_BLO + off) = l;
    }
    __syncthreads();

    {
        int nl = t >> 1;
        int n = n0 + nl;
        int j0 = (t & 1) * 32;
        const float inv = 1.0f / 127.0f;
        float gx = (float)(n >> 7) * inv;
        float gy = (float)(n & 127) * inv;
#pragma unroll
        for (int jj = 0; jj < 32; jj += 2) {
            int j = j0 + jj;
            float v0 = fmaxf(fmaf(gx, sW1[j],     fmaf(gy, sW1[H1D + j],     sB1[j])),     0.0f);
            float v1 = fmaxf(fmaf(gx, sW1[j + 1], fmaf(gy, sW1[H1D + j + 1], sB1[j + 1])), 0.0f);
            __nv_bfloat16 h0, l0, h1v, l1; split1(v0, h0, l0); split1(v1, h1v, l1);
            uint32_t off = (uint32_t)((nl * MSTR + j) * 2);
            *(uint32_t*)(dsm + M_AHI + off) = pack2(h0, h1v);
            *(uint32_t*)(dsm + M_ALO + off) = pack2(l0, l1);
        }
    }
    __syncthreads();

    int m_w = (wid & 3) * 32;
    int j_w = (wid >> 2) * 64;
    int lrow = lane & 15, lcol = (lane >> 4) * 8;
    int grp = lane >> 2, tig = lane & 3;

    float C[2][8][4];
#pragma unroll
    for (int a = 0; a < 2; a++)
#pragma unroll
        for (int b = 0; b < 8; b++)
#pragma unroll
            for (int d = 0; d < 4; d++) C[a][b][d] = 0.0f;

#pragma unroll
    for (int ks = 0; ks < 4; ks++) {
        int c0 = ks * 16;
        uint32_t ah[8], al[8], bh[16], bl[16];
#pragma unroll
        for (int mi = 0; mi < 2; mi++) {
            uint32_t ro = (uint32_t)(((m_w + mi * 16 + lrow) * MSTR + c0 + lcol) * 2);
            ldm4(ah + mi * 4, sb + M_AHI + ro);
            ldm4(al + mi * 4, sb + M_ALO + ro);
        }
#pragma unroll
        for (int q = 0; q < 4; q++) {
            uint32_t ro = (uint32_t)(((j_w + q * 16 + lrow) * MSTR + c0 + lcol) * 2);
            ldm4(bh + q * 4, sb + M_BHI + ro);
            ldm4(bl + q * 4, sb + M_BLO + ro);
        }
#pragma unroll
        for (int mi = 0; mi < 2; mi++)
#pragma unroll
            for (int q = 0; q < 4; q++) {
                mma_bf16(C[mi][2*q],   ah + mi*4, bh[q*4+0], bh[q*4+2]);
                mma_bf16(C[mi][2*q],   ah + mi*4, bl[q*4+0], bl[q*4+2]);
                mma_bf16(C[mi][2*q],   al + mi*4, bh[q*4+0], bh[q*4+2]);
                mma_bf16(C[mi][2*q+1], ah + mi*4, bh[q*4+1], bh[q*4+3]);
                mma_bf16(C[mi][2*q+1], ah + mi*4, bl[q*4+1], bl[q*4+3]);
                mma_bf16(C[mi][2*q+1], al + mi*4, bh[q*4+1], bh[q*4+3]);
            }
    }
    __syncthreads();

    float* sO = (float*)dsm;
#pragma unroll
    for (int mi = 0; mi < 2; mi++)
#pragma unroll
        for (int jj = 0; jj < 8; jj++) {
            int j = j_w + jj * 8 + tig * 2;
            int i = m_w + mi * 16 + grp;
            sO[i * 133 + j]           = C[mi][jj][0];
            sO[i * 133 + j + 1]       = C[mi][jj][1];
            sO[(i + 8) * 133 + j]     = C[mi][jj][2];
            sO[(i + 8) * 133 + j + 1] = C[mi][jj][3];
        }
    __syncthreads();

    if (!psi) {
        for (int idx = t; idx < 16384; idx += 256) {
            int k = idx >> 7, r = idx & 127;
            float v = fmaxf(sO[r * 133 + k] + sB2[k], 0.0f);
            __nv_bfloat16 h, l; split1(v, h, l);
            size_t a = (size_t)k * NX + n0 + r;
            g_Bphi_hi[a] = h;
            g_Bphi_lo[a] = l;
        }
    } else {
        for (int idx = t; idx < 16384; idx += 256) {
            int row = idx >> 7, k = idx & 127;
            float v = fmaxf(sO[row * 133 + k] + sB2[k], 0.0f);
            __nv_bfloat16 h, l; split1(v, h, l);
            size_t a = (size_t)(n0 + row) * H2D + k;
            g_Apsi_hi[a] = h;
            g_Apsi_lo[a] = l;
        }
    }
}

// ---------------- GEMM1 (mma.sync) + fused xsum partials -----------------------------
__global__ __launch_bounds__(256, 2) void k_g1(const float* __restrict__ x)
{
    extern __shared__ char dsm[];
    uint32_t sb = smem_u32(dsm);
    int t = threadIdx.x, wid = t >> 5, lane = t & 31;
    int bi0 = blockIdx.x * 64;
    int n0 = blockIdx.y * 512;
    int m_w = (wid & 1) * 32;
    int j_w = (wid >> 1) * 32;
    int lrow = lane & 15, lcol = (lane >> 4) * 8;
    int grp = lane >> 2, tig = lane & 3;

    float C[2][4][4];
#pragma unroll
    for (int a = 0; a < 2; a++)
#pragma unroll
        for (int b = 0; b < 4; b++)
#pragma unroll
            for (int d = 0; d < 4; d++) C[a][b][d] = 0.0f;

    float xs[8];
#pragma unroll
    for (int i = 0; i < 8; i++) xs[i] = 0.0f;

    for (int ch = 0; ch < 4; ch++) {
        int nb = n0 + ch * 128;
#pragma unroll
        for (int it = 0; it < 8; it++) {
            int idx = t + it * 256;
            int row = idx >> 5, nq = idx & 31;
            float4 v = *(const float4*)(x + (size_t)(bi0 + row) * NX + nb + nq * 4);
            xs[it] += (v.x + v.y) + (v.z + v.w);
            __nv_bfloat16 h0,h1,h2,h3,l0,l1,l2,l3;
            split1(v.x,h0,l0); split1(v.y,h1,l1); split1(v.z,h2,l2); split1(v.w,h3,l3);
            uint32_t off = (uint32_t)(row * ROWB + nq * 8);
            *(uint2*)(dsm + G1_AHI + off) = make_uint2(pack2(h0,h1), pack2(h2,h3));
            *(uint2*)(dsm + G1_ALO + off) = make_uint2(pack2(l0,l1), pack2(l2,l3));
        }
        for (int idx = t; idx < 2048; idx += 256) {
            int row = idx >> 4, n8 = idx & 15;
            size_t ga = (size_t)row * NX + nb + n8 * 8;
            uint32_t off = (uint32_t)(row * ROWB + n8 * 16);
            *(uint4*)(dsm + G1_BHI + off) = *(const uint4*)(g_Bphi_hi + ga);
            *(uint4*)(dsm + G1_BLO + off) = *(const uint4*)(g_Bphi_lo + ga);
        }
        __syncthreads();

#pragma unroll
        for (int ks = 0; ks < 8; ks++) {
            int c0 = ks * 16;
            uint32_t ah[8], al[8], bh[8], bl[8];
#pragma unroll
            for (int mi = 0; mi < 2; mi++) {
                uint32_t ro = (uint32_t)(((m_w + mi * 16 + lrow) * TSTR + c0 + lcol) * 2);
                ldm4(ah + mi * 4, sb + G1_AHI + ro);
                ldm4(al + mi * 4, sb + G1_ALO + ro);
            }
#pragma unroll
            for (int q = 0; q < 2; q++) {
                uint32_t ro = (uint32_t)(((j_w + q * 16 + lrow) * TSTR + c0 + lcol) * 2);
                ldm4(bh + q * 4, sb + G1_BHI + ro);
                ldm4(bl + q * 4, sb + G1_BLO + ro);
            }
#pragma unroll
            for (int mi = 0; mi < 2; mi++)
#pragma unroll
                for (int q = 0; q < 2; q++) {
                    mma_bf16(C[mi][2*q],   ah + mi*4, bh[q*4+0], bh[q*4+2]);
                    mma_bf16(C[mi][2*q],   ah + mi*4, bl[q*4+0], bl[q*4+2]);
                    mma_bf16(C[mi][2*q],   al + mi*4, bh[q*4+0], bh[q*4+2]);
                    mma_bf16(C[mi][2*q+1], ah + mi*4, bh[q*4+1], bh[q*4+3]);
                    mma_bf16(C[mi][2*q+1], ah + mi*4, bl[q*4+1], bl[q*4+3]);
                    mma_bf16(C[mi][2*q+1], al + mi*4, bh[q*4+1], bh[q*4+3]);
                }
        }
        __syncthreads();
    }

#pragma unroll
    for (int mi = 0; mi < 2; mi++)
#pragma unroll
        for (int jj = 0; jj < 4; jj++) {
            int j = j_w + jj * 8 + tig * 2;
            int bi_l = m_w + mi * 16 + grp;
            size_t a0 = ((size_t)blockIdx.y * 256 + bi0 + bi_l) * 128 + j;
            *(float2*)(g_Tpart + a0)          = make_float2(C[mi][jj][0], C[mi][jj][1]);
            *(float2*)(g_Tpart + a0 + 8*128)  = make_float2(C[mi][jj][2], C[mi][jj][3]);
        }

#pragma unroll
    for (int i = 0; i < 8; i++) {
        float v = xs[i];
#pragma unroll
        for (int o = 16; o; o >>= 1) v += __shfl_xor_sync(0xffffffffu, v, o);
        if (lane == 0)
            g_xsumpart[blockIdx.y * 256 + bi0 + wid + 8 * i] = v;
    }
}

// ---------------- reduce split-K -> T[bi][k] + xsum (deterministic) ------------------
__global__ __launch_bounds__(256) void k_reduce()
{
    __shared__ float sm[8][32];
    int t = threadIdx.x, b = blockIdx.x;       // grid 1024
    int p = t >> 5, lane = t & 31;
    int o = b * 32 + lane;
    float s = 0.0f;
#pragma unroll
    for (int sp = 0; sp < 4; sp++)
        s += g_Tpart[(size_t)(p * 4 + sp) * (NBI * H2D) + o];
    sm[p][lane] = s;
    __syncthreads();
    if (p == 0) {
        float r = ((sm[0][lane] + sm[1][lane]) + (sm[2][lane] + sm[3][lane]))
                + ((sm[4][lane] + sm[5][lane]) + (sm[6][lane] + sm[7][lane]));
        g_T[o] = r;
    }
    if (b < 8 && p == 1) {
        int o2 = b * 32 + lane;
        float xsv = 0.0f;
#pragma unroll
        for (int sp = 0; sp < KSPLIT; sp++) xsv += g_xsumpart[sp * 256 + o2];
        g_xsum[o2] = xsv;
    }
}

// ---------------- k_s2: s[b][o*32+i] (grid 256 = bi rows, 128 thr) ----------------
__global__ __launch_bounds__(128) void k_s2(const float* __restrict__ w3p,
                                            const float* __restrict__ b3p)
{
    __shared__ float sT[128];
    __shared__ float sXs;
    int bi = blockIdx.x, t = threadIdx.x;
    int b = bi >> 5, i = bi & 31;
    sT[t] = g_T[bi * 128 + t];
    if (t == 0) sXs = g_xsum[bi];
    __syncthreads();

    int o = t >> 2, q = t & 3;                 // 32 outputs x 4 partials
    int col = o * 32 + i;
    const float* wp = w3p + (size_t)(q * 32) * 1024 + col;
    float acc = 0.0f;
#pragma unroll
    for (int j = 0; j < 32; j++)
        acc = fmaf(sT[q * 32 + j], wp[j * 1024], acc);
    acc += __shfl_xor_sync(0xffffffffu, acc, 1);
    acc += __shfl_xor_sync(0xffffffffu, acc, 2);
    if (q == 0)
        g_S[b * 1024 + col] = acc + b3p[col] * sXs;
}

// ---------------- k_u2: U[bo][k], c[bo] (grid 256 = (b,o), 128 thr) ----------------
__global__ __launch_bounds__(128) void k_u2(const float* __restrict__ w3q,
                                            const float* __restrict__ b3q)
{
    __shared__ float sW[128 * 33];
    __shared__ float sS[32];
    int bo = blockIdx.x, t = threadIdx.x;      // bo = b*32 + o
    int b = bo >> 5, o = bo & 31;
    for (int idx = t; idx < 4096; idx += 128) {
        int i = idx & 31, k = idx >> 5;
        sW[k * 33 + i] = w3q[k * 1024 + o * 32 + i];
    }
    if (t < 32) sS[t] = g_S[b * 1024 + o * 32 + t];
    __syncthreads();

    const float inv = 1.0f / (float)NX;
    {
        int k = t;
        float u = 0.0f;
#pragma unroll
        for (int ii = 0; ii < 32; ii++)
            u = fmaf(sS[ii], sW[k * 33 + ii], u);
        g_U[(size_t)bo * 128 + k] = u * inv;
    }
    if (t < 32) {
        float v = sS[t] * b3q[o * 32 + t];
#pragma unroll
        for (int off = 16; off; off >>= 1) v += __shfl_xor_sync(0xffffffffu, v, off);
        if (t == 0) g_c[bo] = v * inv;
    }
}

// ---------------- GEMM2 (mma.sync): out[bo][m] = psi[m,k] * U[bo,k] + c ----------------
__global__ __launch_bounds__(256, 2) void k_g2(float* __restrict__ out)
{
    extern __shared__ char dsm[];
    __shared__ float sc[64];
    uint32_t sb = smem_u32(dsm);
    int t = threadIdx.x, wid = t >> 5, lane = t & 31;
    int m0 = blockIdx.x * 128;
    int bo0 = blockIdx.y * 64;
    int m_w = (wid & 3) * 32;
    int j_w = (wid >> 2) * 32;
    int lrow = lane & 15, lcol = (lane >> 4) * 8;
    int grp = lane >> 2, tig = lane & 3;

    if (t < 64) sc[t] = g_c[bo0 + t];

    for (int idx = t; idx < 2048; idx += 256) {
        int row = idx >> 4, k8 = idx & 15;
        size_t ga = (size_t)(m0 + row) * H2D + k8 * 8;
        uint32_t off = (uint32_t)(row * ROWB + k8 * 16);
        *(uint4*)(dsm + G2_AHI + off) = *(const uint4*)(g_Apsi_hi + ga);
        *(uint4*)(dsm + G2_ALO + off) = *(const uint4*)(g_Apsi_lo + ga);
    }
    for (int idx = t; idx < 2048; idx += 256) {
        int row = idx >> 5, kq = idx & 31;
        float4 v = *(const float4*)(g_U + (size_t)(bo0 + row) * 128 + kq * 4);
        __nv_bfloat16 h0,h1,h2,h3,l0,l1,l2,l3;
        split1(v.x,h0,l0); split1(v.y,h1,l1); split1(v.z,h2,l2); split1(v.w,h3,l3);
        uint32_t off = (uint32_t)(row * ROWB + kq * 8);
        *(uint2*)(dsm + G2_BHI + off) = make_uint2(pack2(h0,h1), pack2(h2,h3));
        *(uint2*)(dsm + G2_BLO + off) = make_uint2(pack2(l0,l1), pack2(l2,l3));
    }
    __syncthreads();

    float C[2][4][4];
#pragma unroll
    for (int a = 0; a < 2; a++)
#pragma unroll
        for (int b = 0; b < 4; b++)
#pragma unroll
            for (int d = 0; d < 4; d++) C[a][b][d] = 0.0f;

#pragma unroll
    for (int ks = 0; ks < 8; ks++) {
        int c0 = ks * 16;
        uint32_t ah[8], al[8], bh[8], bl[8];
#pragma unroll
        for (int mi = 0; mi < 2; mi++) {
            uint32_t ro = (uint32_t)(((m_w + mi * 16 + lrow) * TSTR + c0 + lcol) * 2);
            ldm4(ah + mi * 4, sb + G2_AHI + ro);
            ldm4(al + mi * 4, sb + G2_ALO + ro);
        }
#pragma unroll
        for (int q = 0; q < 2; q++) {
            uint32_t ro = (uint32_t)(((j_w + q * 16 + lrow) * TSTR + c0 + lcol) * 2);
            ldm4(bh + q * 4, sb + G2_BHI + ro);
            ldm4(bl + q * 4, sb + G2_BLO + ro);
        }
#pragma unroll
        for (int mi = 0; mi < 2; mi++)
#pragma unroll
            for (int q = 0; q < 2; q++) {
                mma_bf16(C[mi][2*q],   ah + mi*4, bh[q*4+0], bh[q*4+2]);
                mma_bf16(C[mi][2*q],   ah + mi*4, bl[q*4+0], bl[q*4+2]);
                mma_bf16(C[mi][2*q],   al + mi*4, bh[q*4+0], bh[q*4+2]);
                mma_bf16(C[mi][2*q+1], ah + mi*4, bh[q*4+1], bh[q*4+3]);
                mma_bf16(C[mi][2*q+1], ah + mi*4, bl[q*4+1], bl[q*4+3]);
                mma_bf16(C[mi][2*q+1], al + mi*4, bh[q*4+1], bh[q*4+3]);
            }
    }
    __syncthreads();

    float* sO = (float*)dsm;
#pragma unroll
    for (int mi = 0; mi < 2; mi++)
#pragma unroll
        for (int jj = 0; jj < 4; jj++) {
            int j = j_w + jj * 8 + tig * 2;
            int i = m_w + mi * 16 + grp;
            sO[j * 132 + i]           = C[mi][jj][0];
            sO[(j + 1) * 132 + i]     = C[mi][jj][1];
            sO[j * 132 + i + 8]       = C[mi][jj][2];
            sO[(j + 1) * 132 + i + 8] = C[mi][jj][3];
        }
    __syncthreads();
    for (int idx = t; idx < 8192; idx += 256) {
        int i = idx & 127, j = idx >> 7;
        out[(size_t)(bo0 + j) * NX + m0 + i] = sO[j * 132 + i] + sc[j];
    }
}

// ---------------- launch ----------------
extern "C" void kernel_launch(void* const* d_in, const int* in_sizes, int n_in,
                              void* d_out, int out_size)
{
    const float* x      = (const float*)d_in[0];
    const float* phi_w1 = (const float*)d_in[1];
    const float* phi_b1 = (const float*)d_in[2];
    const float* phi_w2 = (const float*)d_in[3];
    const float* phi_b2 = (const float*)d_in[4];
    const float* phi_w3 = (const float*)d_in[5];
    const float* phi_b3 = (const float*)d_in[6];
    const float* psi_w1 = (const float*)d_in[7];
    const float* psi_b1 = (const float*)d_in[8];
    const float* psi_w2 = (const float*)d_in[9];
    const float* psi_b2 = (const float*)d_in[10];
    const float* psi_w3 = (const float*)d_in[11];
    const float* psi_b3 = (const float*)d_in[12];
    float* out = (float*)d_out;

    cudaFuncSetAttribute(k_mlp, cudaFuncAttributeMaxDynamicSharedMemorySize, MLP_SMEM);
    cudaFuncSetAttribute(k_g1,  cudaFuncAttributeMaxDynamicSharedMemorySize, G1_SMEM);
    cudaFuncSetAttribute(k_g2,  cudaFuncAttributeMaxDynamicSharedMemorySize, G2_SMEM);

    k_mlp<<<dim3(NX / 128, 2), 256, MLP_SMEM>>>(phi_w1, phi_b1, phi_w2, phi_b2,
                                                psi_w1, psi_b1, psi_w2, psi_b2);
    k_g1<<<dim3(4, KSPLIT), 256, G1_SMEM>>>(x);
    k_reduce<<<1024, 256>>>();
    k_s2<<<NBI, 128>>>(phi_w3, phi_b3);
    k_u2<<<NBO, 128>>>(psi_w3, psi_b3);
    k_g2<<<dim3(NX / 128, 4), 256, G2_SMEM>>>(out);
}

// round 10
// speedup vs baseline: 2.0579x; 1.0294x over previous
#include <cuda_runtime.h>
#include <cuda_bf16.h>
#include <cstdint>

#define NX    16384
#define CI    32
#define CO    32
#define H1D   64
#define H2D   128
#define NBI   256
#define NBO   256
#define KSPLIT 32

// ---------------- device scratch ----------------
__device__ __nv_bfloat16 g_Bphi_hi[H2D * NX];   // [k][n] phi hidden (relu'd), bf16 hi
__device__ __nv_bfloat16 g_Bphi_lo[H2D * NX];   // residual
__device__ __nv_bfloat16 g_Apsi_hi[NX * H2D];   // [m][k] psi hidden, bf16 hi
__device__ __nv_bfloat16 g_Apsi_lo[NX * H2D];
__device__ float g_Tpart[KSPLIT * NBI * H2D];   // [sp][bi][k]  4.2 MB
__device__ float g_xsumpart[KSPLIT * NBI];      // [sp][bi]
__device__ float g_T[NBI * H2D];                // [bi][k]
__device__ float g_xsum[NBI];
__device__ float g_w3pt[CI * H2D * CO];         // [i][k][o]  512 KB
__device__ float g_S[8 * CO * CI];              // [b][o*32+i]
__device__ float g_U[NBO * H2D];                // [b*32+o][k] (scaled 1/NX)
__device__ float g_c[NBO];                      // (scaled 1/NX)

// ---------------- helpers ----------------
__device__ __forceinline__ uint32_t smem_u32(const void* p) {
    uint32_t a;
    asm("{ .reg .u64 t; cvta.to.shared.u64 t, %1; cvt.u32.u64 %0, t; }" : "=r"(a) : "l"(p));
    return a;
}
__device__ __forceinline__ void ldm4(uint32_t* r, uint32_t addr) {
    asm volatile("ldmatrix.sync.aligned.m8n8.x4.shared.b16 {%0,%1,%2,%3}, [%4];"
                 : "=r"(r[0]), "=r"(r[1]), "=r"(r[2]), "=r"(r[3]) : "r"(addr));
}
__device__ __forceinline__ void mma_bf16(float* c, const uint32_t* a, uint32_t b0, uint32_t b1) {
    asm volatile("mma.sync.aligned.m16n8k16.row.col.f32.bf16.bf16.f32 "
                 "{%0,%1,%2,%3}, {%4,%5,%6,%7}, {%8,%9}, {%0,%1,%2,%3};"
                 : "+f"(c[0]), "+f"(c[1]), "+f"(c[2]), "+f"(c[3])
                 : "r"(a[0]), "r"(a[1]), "r"(a[2]), "r"(a[3]), "r"(b0), "r"(b1));
}
__device__ __forceinline__ uint32_t pack2(__nv_bfloat16 a, __nv_bfloat16 b) {
    return (uint32_t)__bfloat16_as_ushort(a) | ((uint32_t)__bfloat16_as_ushort(b) << 16);
}
__device__ __forceinline__ void split1(float v, __nv_bfloat16& h, __nv_bfloat16& l) {
    h = __float2bfloat16(v);
    l = __float2bfloat16(v - __bfloat162float(h));
}

// SMEM tile geometry for GEMM1/2 (bf16): row stride 136 elems (272 B)
#define TSTR 136
#define ROWB 272
// k_g1: A = x (64 rows), B = phi (128 rows)
#define G1_AHI 0
#define G1_ALO 17408
#define G1_BHI 34816
#define G1_BLO 69632
#define G1_SMEM 104448
// k_g2: A = psi (128 rows), B = U (64 rows)
#define G2_AHI 0
#define G2_ALO 34816
#define G2_BHI 69632
#define G2_BLO 87040
#define G2_SMEM 104448
// k_mlp: A = h1 (128 n x 64 j), B = w2T (128 k x 64 j), stride 72 elems (144 B)
#define MSTR 72
#define M_AHI 0
#define M_ALO 18432
#define M_BHI 36864
#define M_BLO 55296
#define MLP_SMEM 73728

// ---------------- K1: coordinate MLPs, layer2 on tensor pipe ----------------
__global__ __launch_bounds__(256) void k_mlp(
    const float* __restrict__ w1p, const float* __restrict__ b1p,
    const float* __restrict__ w2p, const float* __restrict__ b2p,
    const float* __restrict__ w1q, const float* __restrict__ b1q,
    const float* __restrict__ w2q, const float* __restrict__ b2q)
{
    extern __shared__ char dsm[];
    __shared__ float sW1[2 * H1D];
    __shared__ float sB1[H1D];
    __shared__ float sB2[H2D];
    uint32_t sb = smem_u32(dsm);

    const bool psi = (blockIdx.y != 0);
    const float* w1 = psi ? w1q : w1p;
    const float* b1 = psi ? b1q : b1p;
    const float* w2 = psi ? w2q : w2p;
    const float* b2 = psi ? b2q : b2p;

    int t = threadIdx.x, wid = t >> 5, lane = t & 31;
    int n0 = blockIdx.x * 128;

    if (t < 2 * H1D) sW1[t] = w1[t];
    if (t < H1D)     sB1[t] = b1[t];
    if (t < H2D)     sB2[t] = b2[t];

    for (int idx = t; idx < H1D * H2D; idx += 256) {
        int k = idx & 127, j = idx >> 7;
        float v = w2[j * 128 + k];
        __nv_bfloat16 h, l; split1(v, h, l);
        uint32_t off = (uint32_t)((k * MSTR + j) * 2);
        *(__nv_bfloat16*)(dsm + M_BHI + off) = h;
        *(__nv_bfloat16*)(dsm + M_BLO + off) = l;
    }
    __syncthreads();

    {
        int nl = t >> 1;
        int n = n0 + nl;
        int j0 = (t & 1) * 32;
        const float inv = 1.0f / 127.0f;
        float gx = (float)(n >> 7) * inv;
        float gy = (float)(n & 127) * inv;
#pragma unroll
        for (int jj = 0; jj < 32; jj += 2) {
            int j = j0 + jj;
            float v0 = fmaxf(fmaf(gx, sW1[j],     fmaf(gy, sW1[H1D + j],     sB1[j])),     0.0f);
            float v1 = fmaxf(fmaf(gx, sW1[j + 1], fmaf(gy, sW1[H1D + j + 1], sB1[j + 1])), 0.0f);
            __nv_bfloat16 h0, l0, h1v, l1; split1(v0, h0, l0); split1(v1, h1v, l1);
            uint32_t off = (uint32_t)((nl * MSTR + j) * 2);
            *(uint32_t*)(dsm + M_AHI + off) = pack2(h0, h1v);
            *(uint32_t*)(dsm + M_ALO + off) = pack2(l0, l1);
        }
    }
    __syncthreads();

    int m_w = (wid & 3) * 32;
    int j_w = (wid >> 2) * 64;
    int lrow = lane & 15, lcol = (lane >> 4) * 8;
    int grp = lane >> 2, tig = lane & 3;

    float C[2][8][4];
#pragma unroll
    for (int a = 0; a < 2; a++)
#pragma unroll
        for (int b = 0; b < 8; b++)
#pragma unroll
            for (int d = 0; d < 4; d++) C[a][b][d] = 0.0f;

#pragma unroll
    for (int ks = 0; ks < 4; ks++) {
        int c0 = ks * 16;
        uint32_t ah[8], al[8], bh[16], bl[16];
#pragma unroll
        for (int mi = 0; mi < 2; mi++) {
            uint32_t ro = (uint32_t)(((m_w + mi * 16 + lrow) * MSTR + c0 + lcol) * 2);
            ldm4(ah + mi * 4, sb + M_AHI + ro);
            ldm4(al + mi * 4, sb + M_ALO + ro);
        }
#pragma unroll
        for (int q = 0; q < 4; q++) {
            uint32_t ro = (uint32_t)(((j_w + q * 16 + lrow) * MSTR + c0 + lcol) * 2);
            ldm4(bh + q * 4, sb + M_BHI + ro);
            ldm4(bl + q * 4, sb + M_BLO + ro);
        }
#pragma unroll
        for (int mi = 0; mi < 2; mi++)
#pragma unroll
            for (int q = 0; q < 4; q++) {
                mma_bf16(C[mi][2*q],   ah + mi*4, bh[q*4+0], bh[q*4+2]);
                mma_bf16(C[mi][2*q],   ah + mi*4, bl[q*4+0], bl[q*4+2]);
                mma_bf16(C[mi][2*q],   al + mi*4, bh[q*4+0], bh[q*4+2]);
                mma_bf16(C[mi][2*q+1], ah + mi*4, bh[q*4+1], bh[q*4+3]);
                mma_bf16(C[mi][2*q+1], ah + mi*4, bl[q*4+1], bl[q*4+3]);
                mma_bf16(C[mi][2*q+1], al + mi*4, bh[q*4+1], bh[q*4+3]);
            }
    }
    __syncthreads();

    float* sO = (float*)dsm;
#pragma unroll
    for (int mi = 0; mi < 2; mi++)
#pragma unroll
        for (int jj = 0; jj < 8; jj++) {
            int j = j_w + jj * 8 + tig * 2;
            int i = m_w + mi * 16 + grp;
            sO[i * 133 + j]           = C[mi][jj][0];
            sO[i * 133 + j + 1]       = C[mi][jj][1];
            sO[(i + 8) * 133 + j]     = C[mi][jj][2];
            sO[(i + 8) * 133 + j + 1] = C[mi][jj][3];
        }
    __syncthreads();

    if (!psi) {
        for (int idx = t; idx < 16384; idx += 256) {
            int k = idx >> 7, r = idx & 127;
            float v = fmaxf(sO[r * 133 + k] + sB2[k], 0.0f);
            __nv_bfloat16 h, l; split1(v, h, l);
            size_t a = (size_t)k * NX + n0 + r;
            g_Bphi_hi[a] = h;
            g_Bphi_lo[a] = l;
        }
    } else {
        for (int idx = t; idx < 16384; idx += 256) {
            int row = idx >> 7, k = idx & 127;
            float v = fmaxf(sO[row * 133 + k] + sB2[k], 0.0f);
            __nv_bfloat16 h, l; split1(v, h, l);
            size_t a = (size_t)(n0 + row) * H2D + k;
            g_Apsi_hi[a] = h;
            g_Apsi_lo[a] = l;
        }
    }
}

// ---------------- k_tr: w3p[k][o*32+i] -> w3pt[i][k][o] (both sides coalesced) ------
__global__ __launch_bounds__(256) void k_tr(const float* __restrict__ w3p)
{
    __shared__ float sm[32 * 33];          // [o][i] pad 33
    int k = blockIdx.x, t = threadIdx.x;
    for (int it = 0; it < 4; it++) {
        int col = it * 256 + t;            // coalesced read
        sm[(col >> 5) * 33 + (col & 31)] = w3p[k * 1024 + col];
    }
    __syncthreads();
    for (int it = 0; it < 4; it++) {
        int idx = it * 256 + t;
        int i = idx >> 5, o = idx & 31;    // consecutive t -> consecutive o: coalesced write
        g_w3pt[i * 4096 + k * 32 + o] = sm[o * 33 + i];
    }
}

// ---------------- GEMM1 (mma.sync) + fused xsum partials -----------------------------
__global__ __launch_bounds__(256, 2) void k_g1(const float* __restrict__ x)
{
    extern __shared__ char dsm[];
    uint32_t sb = smem_u32(dsm);
    int t = threadIdx.x, wid = t >> 5, lane = t & 31;
    int bi0 = blockIdx.x * 64;
    int n0 = blockIdx.y * 512;
    int m_w = (wid & 1) * 32;
    int j_w = (wid >> 1) * 32;
    int lrow = lane & 15, lcol = (lane >> 4) * 8;
    int grp = lane >> 2, tig = lane & 3;

    float C[2][4][4];
#pragma unroll
    for (int a = 0; a < 2; a++)
#pragma unroll
        for (int b = 0; b < 4; b++)
#pragma unroll
            for (int d = 0; d < 4; d++) C[a][b][d] = 0.0f;

    float xs[8];
#pragma unroll
    for (int i = 0; i < 8; i++) xs[i] = 0.0f;

    for (int ch = 0; ch < 4; ch++) {
        int nb = n0 + ch * 128;
#pragma unroll
        for (int it = 0; it < 8; it++) {
            int idx = t + it * 256;
            int row = idx >> 5, nq = idx & 31;
            float4 v = *(const float4*)(x + (size_t)(bi0 + row) * NX + nb + nq * 4);
            xs[it] += (v.x + v.y) + (v.z + v.w);
            __nv_bfloat16 h0,h1,h2,h3,l0,l1,l2,l3;
            split1(v.x,h0,l0); split1(v.y,h1,l1); split1(v.z,h2,l2); split1(v.w,h3,l3);
            uint32_t off = (uint32_t)(row * ROWB + nq * 8);
            *(uint2*)(dsm + G1_AHI + off) = make_uint2(pack2(h0,h1), pack2(h2,h3));
            *(uint2*)(dsm + G1_ALO + off) = make_uint2(pack2(l0,l1), pack2(l2,l3));
        }
        for (int idx = t; idx < 2048; idx += 256) {
            int row = idx >> 4, n8 = idx & 15;
            size_t ga = (size_t)row * NX + nb + n8 * 8;
            uint32_t off = (uint32_t)(row * ROWB + n8 * 16);
            *(uint4*)(dsm + G1_BHI + off) = *(const uint4*)(g_Bphi_hi + ga);
            *(uint4*)(dsm + G1_BLO + off) = *(const uint4*)(g_Bphi_lo + ga);
        }
        __syncthreads();

#pragma unroll
        for (int ks = 0; ks < 8; ks++) {
            int c0 = ks * 16;
            uint32_t ah[8], al[8], bh[8], bl[8];
#pragma unroll
            for (int mi = 0; mi < 2; mi++) {
                uint32_t ro = (uint32_t)(((m_w + mi * 16 + lrow) * TSTR + c0 + lcol) * 2);
                ldm4(ah + mi * 4, sb + G1_AHI + ro);
                ldm4(al + mi * 4, sb + G1_ALO + ro);
            }
#pragma unroll
            for (int q = 0; q < 2; q++) {
                uint32_t ro = (uint32_t)(((j_w + q * 16 + lrow) * TSTR + c0 + lcol) * 2);
                ldm4(bh + q * 4, sb + G1_BHI + ro);
                ldm4(bl + q * 4, sb + G1_BLO + ro);
            }
#pragma unroll
            for (int mi = 0; mi < 2; mi++)
#pragma unroll
                for (int q = 0; q < 2; q++) {
                    mma_bf16(C[mi][2*q],   ah + mi*4, bh[q*4+0], bh[q*4+2]);
                    mma_bf16(C[mi][2*q],   ah + mi*4, bl[q*4+0], bl[q*4+2]);
                    mma_bf16(C[mi][2*q],   al + mi*4, bh[q*4+0], bh[q*4+2]);
                    mma_bf16(C[mi][2*q+1], ah + mi*4, bh[q*4+1], bh[q*4+3]);
                    mma_bf16(C[mi][2*q+1], ah + mi*4, bl[q*4+1], bl[q*4+3]);
                    mma_bf16(C[mi][2*q+1], al + mi*4, bh[q*4+1], bh[q*4+3]);
                }
        }
        __syncthreads();
    }

#pragma unroll
    for (int mi = 0; mi < 2; mi++)
#pragma unroll
        for (int jj = 0; jj < 4; jj++) {
            int j = j_w + jj * 8 + tig * 2;
            int bi_l = m_w + mi * 16 + grp;
            size_t a0 = ((size_t)blockIdx.y * 256 + bi0 + bi_l) * 128 + j;
            *(float2*)(g_Tpart + a0)          = make_float2(C[mi][jj][0], C[mi][jj][1]);
            *(float2*)(g_Tpart + a0 + 8*128)  = make_float2(C[mi][jj][2], C[mi][jj][3]);
        }

#pragma unroll
    for (int i = 0; i < 8; i++) {
        float v = xs[i];
#pragma unroll
        for (int o = 16; o; o >>= 1) v += __shfl_xor_sync(0xffffffffu, v, o);
        if (lane == 0)
            g_xsumpart[blockIdx.y * 256 + bi0 + wid + 8 * i] = v;
    }
}

// ---------------- reduce split-K -> T[bi][k] + xsum (deterministic) ------------------
__global__ __launch_bounds__(256) void k_reduce()
{
    __shared__ float sm[8][32];
    int t = threadIdx.x, b = blockIdx.x;       // grid 1024
    int p = t >> 5, lane = t & 31;
    int o = b * 32 + lane;
    float s = 0.0f;
#pragma unroll
    for (int sp = 0; sp < 4; sp++)
        s += g_Tpart[(size_t)(p * 4 + sp) * (NBI * H2D) + o];
    sm[p][lane] = s;
    __syncthreads();
    if (p == 0) {
        float r = ((sm[0][lane] + sm[1][lane]) + (sm[2][lane] + sm[3][lane]))
                + ((sm[4][lane] + sm[5][lane]) + (sm[6][lane] + sm[7][lane]));
        g_T[o] = r;
    }
    if (b < 8 && p == 1) {
        int o2 = b * 32 + lane;
        float xsv = 0.0f;
#pragma unroll
        for (int sp = 0; sp < KSPLIT; sp++) xsv += g_xsumpart[sp * 256 + o2];
        g_xsum[o2] = xsv;
    }
}

// ---------------- k_s3: s[b][o*32+i] (grid 256 = bi rows, coalesced w3pt) ------------
__global__ __launch_bounds__(128) void k_s3(const float* __restrict__ b3p)
{
    __shared__ float sT[128];
    __shared__ float sXs;
    __shared__ float smc[4][32];
    int bi = blockIdx.x, t = threadIdx.x;
    int b = bi >> 5, i = bi & 31;
    sT[t] = g_T[bi * 128 + t];
    if (t == 0) sXs = g_xsum[bi];
    __syncthreads();

    int o = t & 31, kq = t >> 5;               // lanes -> o: coalesced w3pt loads
    const float* wp = g_w3pt + (size_t)i * 4096 + (size_t)(kq * 32) * 32 + o;
    float acc = 0.0f;
#pragma unroll
    for (int j = 0; j < 32; j++)
        acc = fmaf(sT[kq * 32 + j], wp[j * 32], acc);
    smc[kq][o] = acc;
    __syncthreads();
    if (t < 32) {
        int col = t * 32 + i;                  // o = t
        float s = (smc[0][t] + smc[1][t]) + (smc[2][t] + smc[3][t]);
        g_S[b * 1024 + col] = s + b3p[col] * sXs;
    }
}

// ---------------- k_u2: U[bo][k], c[bo] (grid 256 = (b,o), 128 thr) ----------------
__global__ __launch_bounds__(128) void k_u2(const float* __restrict__ w3q,
                                            const float* __restrict__ b3q)
{
    __shared__ float sW[128 * 33];
    __shared__ float sS[32];
    int bo = blockIdx.x, t = threadIdx.x;      // bo = b*32 + o
    int b = bo >> 5, o = bo & 31;
    for (int idx = t; idx < 4096; idx += 128) {
        int i = idx & 31, k = idx >> 5;
        sW[k * 33 + i] = w3q[k * 1024 + o * 32 + i];
    }
    if (t < 32) sS[t] = g_S[b * 1024 + o * 32 + t];
    __syncthreads();

    const float inv = 1.0f / (float)NX;
    {
        int k = t;
        float u = 0.0f;
#pragma unroll
        for (int ii = 0; ii < 32; ii++)
            u = fmaf(sS[ii], sW[k * 33 + ii], u);
        g_U[(size_t)bo * 128 + k] = u * inv;
    }
    if (t < 32) {
        float v = sS[t] * b3q[o * 32 + t];
#pragma unroll
        for (int off = 16; off; off >>= 1) v += __shfl_xor_sync(0xffffffffu, v, off);
        if (t == 0) g_c[bo] = v * inv;
    }
}

// ---------------- GEMM2 (mma.sync): out[bo][m] = psi[m,k] * U[bo,k] + c ----------------
__global__ __launch_bounds__(256, 2) void k_g2(float* __restrict__ out)
{
    extern __shared__ char dsm[];
    __shared__ float sc[64];
    uint32_t sb = smem_u32(dsm);
    int t = threadIdx.x, wid = t >> 5, lane = t & 31;
    int m0 = blockIdx.x * 128;
    int bo0 = blockIdx.y * 64;
    int m_w = (wid & 3) * 32;
    int j_w = (wid >> 2) * 32;
    int lrow = lane & 15, lcol = (lane >> 4) * 8;
    int grp = lane >> 2, tig = lane & 3;

    if (t < 64) sc[t] = g_c[bo0 + t];

    for (int idx = t; idx < 2048; idx += 256) {
        int row = idx >> 4, k8 = idx & 15;
        size_t ga = (size_t)(m0 + row) * H2D + k8 * 8;
        uint32_t off = (uint32_t)(row * ROWB + k8 * 16);
        *(uint4*)(dsm + G2_AHI + off) = *(const uint4*)(g_Apsi_hi + ga);
        *(uint4*)(dsm + G2_ALO + off) = *(const uint4*)(g_Apsi_lo + ga);
    }
    for (int idx = t; idx < 2048; idx += 256) {
        int row = idx >> 5, kq = idx & 31;
        float4 v = *(const float4*)(g_U + (size_t)(bo0 + row) * 128 + kq * 4);
        __nv_bfloat16 h0,h1,h2,h3,l0,l1,l2,l3;
        split1(v.x,h0,l0); split1(v.y,h1,l1); split1(v.z,h2,l2); split1(v.w,h3,l3);
        uint32_t off = (uint32_t)(row * ROWB + kq * 8);
        *(uint2*)(dsm + G2_BHI + off) = make_uint2(pack2(h0,h1), pack2(h2,h3));
        *(uint2*)(dsm + G2_BLO + off) = make_uint2(pack2(l0,l1), pack2(l2,l3));
    }
    __syncthreads();

    float C[2][4][4];
#pragma unroll
    for (int a = 0; a < 2; a++)
#pragma unroll
        for (int b = 0; b < 4; b++)
#pragma unroll
            for (int d = 0; d < 4; d++) C[a][b][d] = 0.0f;

#pragma unroll
    for (int ks = 0; ks < 8; ks++) {
        int c0 = ks * 16;
        uint32_t ah[8], al[8], bh[8], bl[8];
#pragma unroll
        for (int mi = 0; mi < 2; mi++) {
            uint32_t ro = (uint32_t)(((m_w + mi * 16 + lrow) * TSTR + c0 + lcol) * 2);
            ldm4(ah + mi * 4, sb + G2_AHI + ro);
            ldm4(al + mi * 4, sb + G2_ALO + ro);
        }
#pragma unroll
        for (int q = 0; q < 2; q++) {
            uint32_t ro = (uint32_t)(((j_w + q * 16 + lrow) * TSTR + c0 + lcol) * 2);
            ldm4(bh + q * 4, sb + G2_BHI + ro);
            ldm4(bl + q * 4, sb + G2_BLO + ro);
        }
#pragma unroll
        for (int mi = 0; mi < 2; mi++)
#pragma unroll
            for (int q = 0; q < 2; q++) {
                mma_bf16(C[mi][2*q],   ah + mi*4, bh[q*4+0], bh[q*4+2]);
                mma_bf16(C[mi][2*q],   ah + mi*4, bl[q*4+0], bl[q*4+2]);
                mma_bf16(C[mi][2*q],   al + mi*4, bh[q*4+0], bh[q*4+2]);
                mma_bf16(C[mi][2*q+1], ah + mi*4, bh[q*4+1], bh[q*4+3]);
                mma_bf16(C[mi][2*q+1], ah + mi*4, bl[q*4+1], bl[q*4+3]);
                mma_bf16(C[mi][2*q+1], al + mi*4, bh[q*4+1], bh[q*4+3]);
            }
    }
    __syncthreads();

    float* sO = (float*)dsm;
#pragma unroll
    for (int mi = 0; mi < 2; mi++)
#pragma unroll
        for (int jj = 0; jj < 4; jj++) {
            int j = j_w + jj * 8 + tig * 2;
            int i = m_w + mi * 16 + grp;
            sO[j * 132 + i]           = C[mi][jj][0];
            sO[(j + 1) * 132 + i]     = C[mi][jj][1];
            sO[j * 132 + i + 8]       = C[mi][jj][2];
            sO[(j + 1) * 132 + i + 8] = C[mi][jj][3];
        }
    __syncthreads();
    for (int idx = t; idx < 8192; idx += 256) {
        int i = idx & 127, j = idx >> 7;
        out[(size_t)(bo0 + j) * NX + m0 + i] = sO[j * 132 + i] + sc[j];
    }
}

// ---------------- launch ----------------
extern "C" void kernel_launch(void* const* d_in, const int* in_sizes, int n_in,
                              void* d_out, int out_size)
{
    const float* x      = (const float*)d_in[0];
    const float* phi_w1 = (const float*)d_in[1];
    const float* phi_b1 = (const float*)d_in[2];
    const float* phi_w2 = (const float*)d_in[3];
    const float* phi_b2 = (const float*)d_in[4];
    const float* phi_w3 = (const float*)d_in[5];
    const float* phi_b3 = (const float*)d_in[6];
    const float* psi_w1 = (const float*)d_in[7];
    const float* psi_b1 = (const float*)d_in[8];
    const float* psi_w2 = (const float*)d_in[9];
    const float* psi_b2 = (const float*)d_in[10];
    const float* psi_w3 = (const float*)d_in[11];
    const float* psi_b3 = (const float*)d_in[12];
    float* out = (float*)d_out;

    cudaFuncSetAttribute(k_mlp, cudaFuncAttributeMaxDynamicSharedMemorySize, MLP_SMEM);
    cudaFuncSetAttribute(k_g1,  cudaFuncAttributeMaxDynamicSharedMemorySize, G1_SMEM);
    cudaFuncSetAttribute(k_g2,  cudaFuncAttributeMaxDynamicSharedMemorySize, G2_SMEM);

    k_tr<<<H2D, 256>>>(phi_w3);
    k_mlp<<<dim3(NX / 128, 2), 256, MLP_SMEM>>>(phi_w1, phi_b1, phi_w2, phi_b2,
                                                psi_w1, psi_b1, psi_w2, psi_b2);
    k_g1<<<dim3(4, KSPLIT), 256, G1_SMEM>>>(x);
    k_reduce<<<1024, 256>>>();
    k_s3<<<NBI, 128>>>(phi_b3);
    k_u2<<<NBO, 128>>>(psi_w3, psi_b3);
    k_g2<<<dim3(NX / 128, 4), 256, G2_SMEM>>>(out);
}

// round 12
// speedup vs baseline: 2.1182x; 1.0293x over previous
#include <cuda_runtime.h>
#include <cuda_bf16.h>
#include <cstdint>

#define NX    16384
#define CI    32
#define CO    32
#define H1D   64
#define H2D   128
#define NBI   256
#define NBO   256
#define KSPLIT 32

// ---------------- device scratch ----------------
__device__ __nv_bfloat16 g_Bphi_hi[H2D * NX];   // [k][n] phi hidden (relu'd), bf16 hi
__device__ __nv_bfloat16 g_Bphi_lo[H2D * NX];   // residual
__device__ __nv_bfloat16 g_Apsi_hi[NX * H2D];   // [m][k] psi hidden, bf16 hi
__device__ __nv_bfloat16 g_Apsi_lo[NX * H2D];
__device__ float g_Tpart[KSPLIT * NBI * H2D];   // [sp][bi][k]  4.2 MB
__device__ float g_xsumpart[KSPLIT * NBI];      // [sp][bi]
__device__ float g_w3pt[CI * H2D * CO];         // [i][k][o]  512 KB
__device__ float g_S[8 * CO * CI];              // [b][o*32+i]
__device__ float g_U[NBO * H2D];                // [b*32+o][k] (scaled 1/NX)
__device__ float g_c[NBO];                      // (scaled 1/NX)

// ---------------- helpers ----------------
__device__ __forceinline__ uint32_t smem_u32(const void* p) {
    uint32_t a;
    asm("{ .reg .u64 t; cvta.to.shared.u64 t, %1; cvt.u32.u64 %0, t; }" : "=r"(a) : "l"(p));
    return a;
}
__device__ __forceinline__ void ldm4(uint32_t* r, uint32_t addr) {
    asm volatile("ldmatrix.sync.aligned.m8n8.x4.shared.b16 {%0,%1,%2,%3}, [%4];"
                 : "=r"(r[0]), "=r"(r[1]), "=r"(r[2]), "=r"(r[3]) : "r"(addr));
}
__device__ __forceinline__ void mma_bf16(float* c, const uint32_t* a, uint32_t b0, uint32_t b1) {
    asm volatile("mma.sync.aligned.m16n8k16.row.col.f32.bf16.bf16.f32 "
                 "{%0,%1,%2,%3}, {%4,%5,%6,%7}, {%8,%9}, {%0,%1,%2,%3};"
                 : "+f"(c[0]), "+f"(c[1]), "+f"(c[2]), "+f"(c[3])
                 : "r"(a[0]), "r"(a[1]), "r"(a[2]), "r"(a[3]), "r"(b0), "r"(b1));
}
__device__ __forceinline__ uint32_t pack2(__nv_bfloat16 a, __nv_bfloat16 b) {
    return (uint32_t)__bfloat16_as_ushort(a) | ((uint32_t)__bfloat16_as_ushort(b) << 16);
}
__device__ __forceinline__ void split1(float v, __nv_bfloat16& h, __nv_bfloat16& l) {
    h = __float2bfloat16(v);
    l = __float2bfloat16(v - __bfloat162float(h));
}

// SMEM tile geometry for GEMM1/2 (bf16): row stride 136 elems (272 B)
#define TSTR 136
#define ROWB 272
// k_g1: A = x (64 rows), B = phi (128 rows)
#define G1_AHI 0
#define G1_ALO 17408
#define G1_BHI 34816
#define G1_BLO 69632
#define G1_SMEM 104448
// k_g2: A = psi (128 rows), B = U (64 rows)
#define G2_AHI 0
#define G2_ALO 34816
#define G2_BHI 69632
#define G2_BLO 87040
#define G2_SMEM 104448
// k_mlp: A = h1 (128 n x 64 j), B = w2T (128 k x 64 j), stride 72 elems (144 B)
#define MSTR 72
#define M_AHI 0
#define M_ALO 18432
#define M_BHI 36864
#define M_BLO 55296
#define MLP_SMEM 73728

// ---------------- K1: coordinate MLPs, layer2 on tensor pipe ----------------
__global__ __launch_bounds__(256) void k_mlp(
    const float* __restrict__ w1p, const float* __restrict__ b1p,
    const float* __restrict__ w2p, const float* __restrict__ b2p,
    const float* __restrict__ w1q, const float* __restrict__ b1q,
    const float* __restrict__ w2q, const float* __restrict__ b2q)
{
    extern __shared__ char dsm[];
    __shared__ float sW1[2 * H1D];
    __shared__ float sB1[H1D];
    __shared__ float sB2[H2D];
    uint32_t sb = smem_u32(dsm);

    const bool psi = (blockIdx.y != 0);
    const float* w1 = psi ? w1q : w1p;
    const float* b1 = psi ? b1q : b1p;
    const float* w2 = psi ? w2q : w2p;
    const float* b2 = psi ? b2q : b2p;

    int t = threadIdx.x, wid = t >> 5, lane = t & 31;
    int n0 = blockIdx.x * 128;

    if (t < 2 * H1D) sW1[t] = w1[t];
    if (t < H1D)     sB1[t] = b1[t];
    if (t < H2D)     sB2[t] = b2[t];

    for (int idx = t; idx < H1D * H2D; idx += 256) {
        int k = idx & 127, j = idx >> 7;
        float v = w2[j * 128 + k];
        __nv_bfloat16 h, l; split1(v, h, l);
        uint32_t off = (uint32_t)((k * MSTR + j) * 2);
        *(__nv_bfloat16*)(dsm + M_BHI + off) = h;
        *(__nv_bfloat16*)(dsm + M_BLO + off) = l;
    }
    __syncthreads();

    {
        int nl = t >> 1;
        int n = n0 + nl;
        int j0 = (t & 1) * 32;
        const float inv = 1.0f / 127.0f;
        float gx = (float)(n >> 7) * inv;
        float gy = (float)(n & 127) * inv;
#pragma unroll
        for (int jj = 0; jj < 32; jj += 2) {
            int j = j0 + jj;
            float v0 = fmaxf(fmaf(gx, sW1[j],     fmaf(gy, sW1[H1D + j],     sB1[j])),     0.0f);
            float v1 = fmaxf(fmaf(gx, sW1[j + 1], fmaf(gy, sW1[H1D + j + 1], sB1[j + 1])), 0.0f);
            __nv_bfloat16 h0, l0, h1v, l1; split1(v0, h0, l0); split1(v1, h1v, l1);
            uint32_t off = (uint32_t)((nl * MSTR + j) * 2);
            *(uint32_t*)(dsm + M_AHI + off) = pack2(h0, h1v);
            *(uint32_t*)(dsm + M_ALO + off) = pack2(l0, l1);
        }
    }
    __syncthreads();

    int m_w = (wid & 3) * 32;
    int j_w = (wid >> 2) * 64;
    int lrow = lane & 15, lcol = (lane >> 4) * 8;
    int grp = lane >> 2, tig = lane & 3;

    float C[2][8][4];
#pragma unroll
    for (int a = 0; a < 2; a++)
#pragma unroll
        for (int b = 0; b < 8; b++)
#pragma unroll
            for (int d = 0; d < 4; d++) C[a][b][d] = 0.0f;

#pragma unroll
    for (int ks = 0; ks < 4; ks++) {
        int c0 = ks * 16;
        uint32_t ah[8], al[8], bh[16], bl[16];
#pragma unroll
        for (int mi = 0; mi < 2; mi++) {
            uint32_t ro = (uint32_t)(((m_w + mi * 16 + lrow) * MSTR + c0 + lcol) * 2);
            ldm4(ah + mi * 4, sb + M_AHI + ro);
            ldm4(al + mi * 4, sb + M_ALO + ro);
        }
#pragma unroll
        for (int q = 0; q < 4; q++) {
            uint32_t ro = (uint32_t)(((j_w + q * 16 + lrow) * MSTR + c0 + lcol) * 2);
            ldm4(bh + q * 4, sb + M_BHI + ro);
            ldm4(bl + q * 4, sb + M_BLO + ro);
        }
#pragma unroll
        for (int mi = 0; mi < 2; mi++)
#pragma unroll
            for (int q = 0; q < 4; q++) {
                mma_bf16(C[mi][2*q],   ah + mi*4, bh[q*4+0], bh[q*4+2]);
                mma_bf16(C[mi][2*q],   ah + mi*4, bl[q*4+0], bl[q*4+2]);
                mma_bf16(C[mi][2*q],   al + mi*4, bh[q*4+0], bh[q*4+2]);
                mma_bf16(C[mi][2*q+1], ah + mi*4, bh[q*4+1], bh[q*4+3]);
                mma_bf16(C[mi][2*q+1], ah + mi*4, bl[q*4+1], bl[q*4+3]);
                mma_bf16(C[mi][2*q+1], al + mi*4, bh[q*4+1], bh[q*4+3]);
            }
    }
    __syncthreads();

    float* sO = (float*)dsm;
#pragma unroll
    for (int mi = 0; mi < 2; mi++)
#pragma unroll
        for (int jj = 0; jj < 8; jj++) {
            int j = j_w + jj * 8 + tig * 2;
            int i = m_w + mi * 16 + grp;
            sO[i * 133 + j]           = C[mi][jj][0];
            sO[i * 133 + j + 1]       = C[mi][jj][1];
            sO[(i + 8) * 133 + j]     = C[mi][jj][2];
            sO[(i + 8) * 133 + j + 1] = C[mi][jj][3];
        }
    __syncthreads();

    if (!psi) {
        for (int idx = t; idx < 16384; idx += 256) {
            int k = idx >> 7, r = idx & 127;
            float v = fmaxf(sO[r * 133 + k] + sB2[k], 0.0f);
            __nv_bfloat16 h, l; split1(v, h, l);
            size_t a = (size_t)k * NX + n0 + r;
            g_Bphi_hi[a] = h;
            g_Bphi_lo[a] = l;
        }
    } else {
        for (int idx = t; idx < 16384; idx += 256) {
            int row = idx >> 7, k = idx & 127;
            float v = fmaxf(sO[row * 133 + k] + sB2[k], 0.0f);
            __nv_bfloat16 h, l; split1(v, h, l);
            size_t a = (size_t)(n0 + row) * H2D + k;
            g_Apsi_hi[a] = h;
            g_Apsi_lo[a] = l;
        }
    }
}

// ---------------- k_tr: w3p[k][o*32+i] -> w3pt[i][k][o] (both sides coalesced) ------
__global__ __launch_bounds__(256) void k_tr(const float* __restrict__ w3p)
{
    __shared__ float sm[32 * 33];          // [o][i] pad 33
    int k = blockIdx.x, t = threadIdx.x;
    for (int it = 0; it < 4; it++) {
        int col = it * 256 + t;            // coalesced read
        sm[(col >> 5) * 33 + (col & 31)] = w3p[k * 1024 + col];
    }
    __syncthreads();
    for (int it = 0; it < 4; it++) {
        int idx = it * 256 + t;
        int i = idx >> 5, o = idx & 31;    // consecutive t -> consecutive o: coalesced write
        g_w3pt[i * 4096 + k * 32 + o] = sm[o * 33 + i];
    }
}

// ---------------- GEMM1 (mma.sync) + fused xsum partials -----------------------------
__global__ __launch_bounds__(256, 2) void k_g1(const float* __restrict__ x)
{
    extern __shared__ char dsm[];
    uint32_t sb = smem_u32(dsm);
    int t = threadIdx.x, wid = t >> 5, lane = t & 31;
    int bi0 = blockIdx.x * 64;
    int n0 = blockIdx.y * 512;
    int m_w = (wid & 1) * 32;
    int j_w = (wid >> 1) * 32;
    int lrow = lane & 15, lcol = (lane >> 4) * 8;
    int grp = lane >> 2, tig = lane & 3;

    float C[2][4][4];
#pragma unroll
    for (int a = 0; a < 2; a++)
#pragma unroll
        for (int b = 0; b < 4; b++)
#pragma unroll
            for (int d = 0; d < 4; d++) C[a][b][d] = 0.0f;

    float xs[8];
#pragma unroll
    for (int i = 0; i < 8; i++) xs[i] = 0.0f;

    for (int ch = 0; ch < 4; ch++) {
        int nb = n0 + ch * 128;
#pragma unroll
        for (int it = 0; it < 8; it++) {
            int idx = t + it * 256;
            int row = idx >> 5, nq = idx & 31;
            float4 v = *(const float4*)(x + (size_t)(bi0 + row) * NX + nb + nq * 4);
            xs[it] += (v.x + v.y) + (v.z + v.w);
            __nv_bfloat16 h0,h1,h2,h3,l0,l1,l2,l3;
            split1(v.x,h0,l0); split1(v.y,h1,l1); split1(v.z,h2,l2); split1(v.w,h3,l3);
            uint32_t off = (uint32_t)(row * ROWB + nq * 8);
            *(uint2*)(dsm + G1_AHI + off) = make_uint2(pack2(h0,h1), pack2(h2,h3));
            *(uint2*)(dsm + G1_ALO + off) = make_uint2(pack2(l0,l1), pack2(l2,l3));
        }
        for (int idx = t; idx < 2048; idx += 256) {
            int row = idx >> 4, n8 = idx & 15;
            size_t ga = (size_t)row * NX + nb + n8 * 8;
            uint32_t off = (uint32_t)(row * ROWB + n8 * 16);
            *(uint4*)(dsm + G1_BHI + off) = *(const uint4*)(g_Bphi_hi + ga);
            *(uint4*)(dsm + G1_BLO + off) = *(const uint4*)(g_Bphi_lo + ga);
        }
        __syncthreads();

#pragma unroll
        for (int ks = 0; ks < 8; ks++) {
            int c0 = ks * 16;
            uint32_t ah[8], al[8], bh[8], bl[8];
#pragma unroll
            for (int mi = 0; mi < 2; mi++) {
                uint32_t ro = (uint32_t)(((m_w + mi * 16 + lrow) * TSTR + c0 + lcol) * 2);
                ldm4(ah + mi * 4, sb + G1_AHI + ro);
                ldm4(al + mi * 4, sb + G1_ALO + ro);
            }
#pragma unroll
            for (int q = 0; q < 2; q++) {
                uint32_t ro = (uint32_t)(((j_w + q * 16 + lrow) * TSTR + c0 + lcol) * 2);
                ldm4(bh + q * 4, sb + G1_BHI + ro);
                ldm4(bl + q * 4, sb + G1_BLO + ro);
            }
#pragma unroll
            for (int mi = 0; mi < 2; mi++)
#pragma unroll
                for (int q = 0; q < 2; q++) {
                    mma_bf16(C[mi][2*q],   ah + mi*4, bh[q*4+0], bh[q*4+2]);
                    mma_bf16(C[mi][2*q],   ah + mi*4, bl[q*4+0], bl[q*4+2]);
                    mma_bf16(C[mi][2*q],   al + mi*4, bh[q*4+0], bh[q*4+2]);
                    mma_bf16(C[mi][2*q+1], ah + mi*4, bh[q*4+1], bh[q*4+3]);
                    mma_bf16(C[mi][2*q+1], ah + mi*4, bl[q*4+1], bl[q*4+3]);
                    mma_bf16(C[mi][2*q+1], al + mi*4, bh[q*4+1], bh[q*4+3]);
                }
        }
        __syncthreads();
    }

#pragma unroll
    for (int mi = 0; mi < 2; mi++)
#pragma unroll
        for (int jj = 0; jj < 4; jj++) {
            int j = j_w + jj * 8 + tig * 2;
            int bi_l = m_w + mi * 16 + grp;
            size_t a0 = ((size_t)blockIdx.y * 256 + bi0 + bi_l) * 128 + j;
            *(float2*)(g_Tpart + a0)          = make_float2(C[mi][jj][0], C[mi][jj][1]);
            *(float2*)(g_Tpart + a0 + 8*128)  = make_float2(C[mi][jj][2], C[mi][jj][3]);
        }

#pragma unroll
    for (int i = 0; i < 8; i++) {
        float v = xs[i];
#pragma unroll
        for (int o = 16; o; o >>= 1) v += __shfl_xor_sync(0xffffffffu, v, o);
        if (lane == 0)
            g_xsumpart[blockIdx.y * 256 + bi0 + wid + 8 * i] = v;
    }
}

// ---------------- k_s3: fused split-K reduce + s[b][o*32+i] (grid 256 = bi rows) -----
__global__ __launch_bounds__(128) void k_s3(const float* __restrict__ b3p)
{
    __shared__ float sT[128];
    __shared__ float sXs;
    __shared__ float smc[4][32];
    int bi = blockIdx.x, t = threadIdx.x;
    int b = bi >> 5, i = bi & 31;

    // reduce Tpart over sp (coalesced 512B rows; 32 independent loads in flight)
    {
        float acc = 0.0f;
        const float* tp = g_Tpart + (size_t)bi * 128 + t;
#pragma unroll
        for (int sp = 0; sp < KSPLIT; sp++)
            acc += tp[(size_t)sp * (NBI * H2D)];
        sT[t] = acc;
    }
    // xsum for this bi (fixed-order warp reduce, deterministic)
    if (t < 32) {
        float v = g_xsumpart[t * 256 + bi];
#pragma unroll
        for (int off = 16; off; off >>= 1) v += __shfl_xor_sync(0xffffffffu, v, off);
        if (t == 0) sXs = v;
    }
    __syncthreads();

    int o = t & 31, kq = t >> 5;               // lanes -> o: coalesced w3pt loads
    const float* wp = g_w3pt + (size_t)i * 4096 + (size_t)(kq * 32) * 32 + o;
    float acc = 0.0f;
#pragma unroll
    for (int j = 0; j < 32; j++)
        acc = fmaf(sT[kq * 32 + j], wp[j * 32], acc);
    smc[kq][o] = acc;
    __syncthreads();
    if (t < 32) {
        int col = t * 32 + i;                  // o = t
        float s = (smc[0][t] + smc[1][t]) + (smc[2][t] + smc[3][t]);
        g_S[b * 1024 + col] = s + b3p[col] * sXs;
    }
}

// ---------------- k_u2: U[bo][k], c[bo] (grid 256 = (b,o), 128 thr) ----------------
__global__ __launch_bounds__(128) void k_u2(const float* __restrict__ w3q,
                                            const float* __restrict__ b3q)
{
    __shared__ float sW[128 * 33];
    __shared__ float sS[32];
    int bo = blockIdx.x, t = threadIdx.x;      // bo = b*32 + o
    int b = bo >> 5, o = bo & 31;
    for (int idx = t; idx < 4096; idx += 128) {
        int i = idx & 31, k = idx >> 5;
        sW[k * 33 + i] = w3q[k * 1024 + o * 32 + i];
    }
    if (t < 32) sS[t] = g_S[b * 1024 + o * 32 + t];
    __syncthreads();

    const float inv = 1.0f / (float)NX;
    {
        int k = t;
        float u = 0.0f;
#pragma unroll
        for (int ii = 0; ii < 32; ii++)
            u = fmaf(sS[ii], sW[k * 33 + ii], u);
        g_U[(size_t)bo * 128 + k] = u * inv;
    }
    if (t < 32) {
        float v = sS[t] * b3q[o * 32 + t];
#pragma unroll
        for (int off = 16; off; off >>= 1) v += __shfl_xor_sync(0xffffffffu, v, off);
        if (t == 0) g_c[bo] = v * inv;
    }
}

// ---------------- GEMM2 (mma.sync): out[bo][m] = psi[m,k] * U[bo,k] + c ----------------
__global__ __launch_bounds__(256, 2) void k_g2(float* __restrict__ out)
{
    extern __shared__ char dsm[];
    __shared__ float sc[64];
    uint32_t sb = smem_u32(dsm);
    int t = threadIdx.x, wid = t >> 5, lane = t & 31;
    int m0 = blockIdx.x * 128;
    int bo0 = blockIdx.y * 64;
    int m_w = (wid & 3) * 32;
    int j_w = (wid >> 2) * 32;
    int lrow = lane & 15, lcol = (lane >> 4) * 8;
    int grp = lane >> 2, tig = lane & 3;

    if (t < 64) sc[t] = g_c[bo0 + t];

    for (int idx = t; idx < 2048; idx += 256) {
        int row = idx >> 4, k8 = idx & 15;
        size_t ga = (size_t)(m0 + row) * H2D + k8 * 8;
        uint32_t off = (uint32_t)(row * ROWB + k8 * 16);
        *(uint4*)(dsm + G2_AHI + off) = *(const uint4*)(g_Apsi_hi + ga);
        *(uint4*)(dsm + G2_ALO + off) = *(const uint4*)(g_Apsi_lo + ga);
    }
    for (int idx = t; idx < 2048; idx += 256) {
        int row = idx >> 5, kq = idx & 31;
        float4 v = *(const float4*)(g_U + (size_t)(bo0 + row) * 128 + kq * 4);
        __nv_bfloat16 h0,h1,h2,h3,l0,l1,l2,l3;
        split1(v.x,h0,l0); split1(v.y,h1,l1); split1(v.z,h2,l2); split1(v.w,h3,l3);
        uint32_t off = (uint32_t)(row * ROWB + kq * 8);
        *(uint2*)(dsm + G2_BHI + off) = make_uint2(pack2(h0,h1), pack2(h2,h3));
        *(uint2*)(dsm + G2_BLO + off) = make_uint2(pack2(l0,l1), pack2(l2,l3));
    }
    __syncthreads();

    float C[2][4][4];
#pragma unroll
    for (int a = 0; a < 2; a++)
#pragma unroll
        for (int b = 0; b < 4; b++)
#pragma unroll
            for (int d = 0; d < 4; d++) C[a][b][d] = 0.0f;

#pragma unroll
    for (int ks = 0; ks < 8; ks++) {
        int c0 = ks * 16;
        uint32_t ah[8], al[8], bh[8], bl[8];
#pragma unroll
        for (int mi = 0; mi < 2; mi++) {
            uint32_t ro = (uint32_t)(((m_w + mi * 16 + lrow) * TSTR + c0 + lcol) * 2);
            ldm4(ah + mi * 4, sb + G2_AHI + ro);
            ldm4(al + mi * 4, sb + G2_ALO + ro);
        }
#pragma unroll
        for (int q = 0; q < 2; q++) {
            uint32_t ro = (uint32_t)(((j_w + q * 16 + lrow) * TSTR + c0 + lcol) * 2);
            ldm4(bh + q * 4, sb + G2_BHI + ro);
            ldm4(bl + q * 4, sb + G2_BLO + ro);
        }
#pragma unroll
        for (int mi = 0; mi < 2; mi++)
#pragma unroll
            for (int q = 0; q < 2; q++) {
                mma_bf16(C[mi][2*q],   ah + mi*4, bh[q*4+0], bh[q*4+2]);
                mma_bf16(C[mi][2*q],   ah + mi*4, bl[q*4+0], bl[q*4+2]);
                mma_bf16(C[mi][2*q],   al + mi*4, bh[q*4+0], bh[q*4+2]);
                mma_bf16(C[mi][2*q+1], ah + mi*4, bh[q*4+1], bh[q*4+3]);
                mma_bf16(C[mi][2*q+1], ah + mi*4, bl[q*4+1], bl[q*4+3]);
                mma_bf16(C[mi][2*q+1], al + mi*4, bh[q*4+1], bh[q*4+3]);
            }
    }
    __syncthreads();

    float* sO = (float*)dsm;
#pragma unroll
    for (int mi = 0; mi < 2; mi++)
#pragma unroll
        for (int jj = 0; jj < 4; jj++) {
            int j = j_w + jj * 8 + tig * 2;
            int i = m_w + mi * 16 + grp;
            sO[j * 132 + i]           = C[mi][jj][0];
            sO[(j + 1) * 132 + i]     = C[mi][jj][1];
            sO[j * 132 + i + 8]       = C[mi][jj][2];
            sO[(j + 1) * 132 + i + 8] = C[mi][jj][3];
        }
    __syncthreads();
    for (int idx = t; idx < 8192; idx += 256) {
        int i = idx & 127, j = idx >> 7;
        out[(size_t)(bo0 + j) * NX + m0 + i] = sO[j * 132 + i] + sc[j];
    }
}

// ---------------- launch ----------------
extern "C" void kernel_launch(void* const* d_in, const int* in_sizes, int n_in,
                              void* d_out, int out_size)
{
    const float* x      = (const float*)d_in[0];
    const float* phi_w1 = (const float*)d_in[1];
    const float* phi_b1 = (const float*)d_in[2];
    const float* phi_w2 = (const float*)d_in[3];
    const float* phi_b2 = (const float*)d_in[4];
    const float* phi_w3 = (const float*)d_in[5];
    const float* phi_b3 = (const float*)d_in[6];
    const float* psi_w1 = (const float*)d_in[7];
    const float* psi_b1 = (const float*)d_in[8];
    const float* psi_w2 = (const float*)d_in[9];
    const float* psi_b2 = (const float*)d_in[10];
    const float* psi_w3 = (const float*)d_in[11];
    const float* psi_b3 = (const float*)d_in[12];
    float* out = (float*)d_out;

    cudaFuncSetAttribute(k_mlp, cudaFuncAttributeMaxDynamicSharedMemorySize, MLP_SMEM);
    cudaFuncSetAttribute(k_g1,  cudaFuncAttributeMaxDynamicSharedMemorySize, G1_SMEM);
    cudaFuncSetAttribute(k_g2,  cudaFuncAttributeMaxDynamicSharedMemorySize, G2_SMEM);

    k_tr<<<H2D, 256>>>(phi_w3);
    k_mlp<<<dim3(NX / 128, 2), 256, MLP_SMEM>>>(phi_w1, phi_b1, phi_w2, phi_b2,
                                                psi_w1, psi_b1, psi_w2, psi_b2);
    k_g1<<<dim3(4, KSPLIT), 256, G1_SMEM>>>(x);
    k_s3<<<NBI, 128>>>(phi_b3);
    k_u2<<<NBO, 128>>>(psi_w3, psi_b3);
    k_g2<<<dim3(NX / 128, 4), 256, G2_SMEM>>>(out);
}